// round 1
// baseline (speedup 1.0000x reference)
#include <cuda_runtime.h>
#include <cuda_bf16.h>

#define N0 50000
#define N1 12500
#define N2 3125
#define E0 800000
#define E1 200000
#define E2 50000
#define D 128

// ---------------- scratch (device globals; no allocation allowed) ----------------
__device__ float g_t[N0 * D];      // GEMM output (max N0 rows)
__device__ float g_enc0[N0 * D];   // encoder feature level 0
__device__ float g_enc1[N1 * D];   // encoder feature level 1
__device__ float g_h[N0 * D];      // ping
__device__ float g_h2[N0 * D];     // pong

// CSR per level (by target/col), edges only (self-loops handled analytically)
__device__ int   g_deg0[N0], g_rp0[N0 + 1], g_cur0[N0], g_src0[E0];
__device__ float g_dis0[N0];
__device__ int   g_deg1[N1], g_rp1[N1 + 1], g_cur1[N1], g_src1[E1];
__device__ float g_dis1[N1];
__device__ int   g_deg2[N2], g_rp2[N2 + 1], g_cur2[N2], g_src2[E2];
__device__ float g_dis2[N2];

// ---------------- small utility kernels ----------------
__global__ void zero_int_k(int* p, int n) {
    int i = blockIdx.x * blockDim.x + threadIdx.x;
    if (i < n) p[i] = 0;
}

__global__ void zero_float_k(float* p, int n) {
    int i = blockIdx.x * blockDim.x + threadIdx.x;
    if (i < n) p[i] = 0.0f;
}

// histogram of in-degree (edge targets)
__global__ void hist_k(const int* __restrict__ col, int E, int* __restrict__ deg) {
    int e = blockIdx.x * blockDim.x + threadIdx.x;
    if (e < E) atomicAdd(&deg[col[e]], 1);
}

// single-block exclusive scan; also produces dis = rsqrt(deg+1) and cursor copy
__global__ void scan_k(const int* __restrict__ deg, int* __restrict__ rp,
                       int* __restrict__ cur, float* __restrict__ dis, int n) {
    __shared__ int sdata[1024];
    __shared__ int s_base;
    int tid = threadIdx.x;
    if (tid == 0) s_base = 0;
    __syncthreads();
    for (int start = 0; start < n; start += 1024) {
        int i = start + tid;
        int v = (i < n) ? deg[i] : 0;
        sdata[tid] = v;
        __syncthreads();
        for (int off = 1; off < 1024; off <<= 1) {
            int t = (tid >= off) ? sdata[tid - off] : 0;
            __syncthreads();
            sdata[tid] += t;
            __syncthreads();
        }
        int excl = sdata[tid] - v;
        if (i < n) {
            int base = s_base + excl;
            rp[i]  = base;
            cur[i] = base;
            dis[i] = rsqrtf((float)(v + 1));
        }
        __syncthreads();
        if (tid == 1023) s_base += sdata[1023];
        __syncthreads();
    }
    if (tid == 0) rp[n] = s_base;
}

// scatter edge sources into CSR buckets
__global__ void scatter_k(const int* __restrict__ row, const int* __restrict__ col,
                          int E, int* __restrict__ cur, int* __restrict__ src) {
    int e = blockIdx.x * blockDim.x + threadIdx.x;
    if (e < E) {
        int d = col[e];
        int pos = atomicAdd(&cur[d], 1);
        src[pos] = row[e];
    }
}

// ---------------- GEMM: C[rows x 128] = A[rows x 128] @ W[128 x 128] ----------------
// BM=64, BN=128, BK=32; 256 threads; thread tile 4x8
__global__ __launch_bounds__(256) void gemm128_k(const float* __restrict__ A,
                                                 const float* __restrict__ W,
                                                 float* __restrict__ C, int rows) {
    __shared__ float As[64 * 32];
    __shared__ float Ws[32 * 128];
    int tid = threadIdx.x;
    int row0 = blockIdx.x * 64;
    int tr = tid >> 4;   // 0..15 -> rows tr*4..tr*4+3
    int tc = tid & 15;   // 0..15 -> cols tc*8..tc*8+7

    float acc[4][8];
#pragma unroll
    for (int i = 0; i < 4; i++)
#pragma unroll
        for (int j = 0; j < 8; j++) acc[i][j] = 0.0f;

    for (int k0 = 0; k0 < 128; k0 += 32) {
        // A tile 64x32 (512 float4)
#pragma unroll
        for (int j = 0; j < 2; j++) {
            int idx = tid + j * 256;
            int r = idx >> 3;
            int kk = (idx & 7) << 2;
            float4 v;
            int gr = row0 + r;
            if (gr < rows) v = *(const float4*)(A + (size_t)gr * D + k0 + kk);
            else v = make_float4(0.f, 0.f, 0.f, 0.f);
            *(float4*)(As + r * 32 + kk) = v;
        }
        // W tile 32x128 (1024 float4)
#pragma unroll
        for (int j = 0; j < 4; j++) {
            int idx = tid + j * 256;
            int k = idx >> 5;
            int c = (idx & 31) << 2;
            *(float4*)(Ws + k * 128 + c) = *(const float4*)(W + (size_t)(k0 + k) * D + c);
        }
        __syncthreads();
#pragma unroll
        for (int kk = 0; kk < 32; kk++) {
            float a[4], w[8];
#pragma unroll
            for (int i = 0; i < 4; i++) a[i] = As[(tr * 4 + i) * 32 + kk];
            float4 w0 = *(float4*)(Ws + kk * 128 + tc * 8);
            float4 w1 = *(float4*)(Ws + kk * 128 + tc * 8 + 4);
            w[0] = w0.x; w[1] = w0.y; w[2] = w0.z; w[3] = w0.w;
            w[4] = w1.x; w[5] = w1.y; w[6] = w1.z; w[7] = w1.w;
#pragma unroll
            for (int i = 0; i < 4; i++)
#pragma unroll
                for (int j = 0; j < 8; j++) acc[i][j] += a[i] * w[j];
        }
        __syncthreads();
    }
#pragma unroll
    for (int i = 0; i < 4; i++) {
        int gr = row0 + tr * 4 + i;
        if (gr < rows) {
            float4 o0 = make_float4(acc[i][0], acc[i][1], acc[i][2], acc[i][3]);
            float4 o1 = make_float4(acc[i][4], acc[i][5], acc[i][6], acc[i][7]);
            *(float4*)(C + (size_t)gr * D + tc * 8)     = o0;
            *(float4*)(C + (size_t)gr * D + tc * 8 + 4) = o1;
        }
    }
}

// ---------------- aggregation: out[d] = relu( sum_{e:col=d} dis[s]*dis[d]*t[clamp(s)]
//                                              + dis[d]^2 * t[clamp(d)] + bias ) ----
__global__ void agg_k(const float* __restrict__ t, int h_rows,
                      const int* __restrict__ rp, const int* __restrict__ src,
                      const float* __restrict__ dis, int n,
                      const float* __restrict__ bias, float* __restrict__ out) {
    int warp = (blockIdx.x * blockDim.x + threadIdx.x) >> 5;
    int lane = threadIdx.x & 31;
    if (warp >= n) return;
    int dst = warp;
    float dd = dis[dst];
    int hc = h_rows - 1;
    int sd = min(dst, hc);
    float4 v = ((const float4*)(t + (size_t)sd * D))[lane];
    float w = dd * dd;
    float4 acc;
    acc.x = w * v.x; acc.y = w * v.y; acc.z = w * v.z; acc.w = w * v.w;
    int beg = rp[dst], end = rp[dst + 1];
    for (int e = beg; e < end; e++) {
        int s = src[e];
        float w2 = dis[s] * dd;
        float4 u = ((const float4*)(t + (size_t)min(s, hc) * D))[lane];
        acc.x += w2 * u.x; acc.y += w2 * u.y; acc.z += w2 * u.z; acc.w += w2 * u.w;
    }
    float4 b = ((const float4*)bias)[lane];
    acc.x = fmaxf(acc.x + b.x, 0.f);
    acc.y = fmaxf(acc.y + b.y, 0.f);
    acc.z = fmaxf(acc.z + b.z, 0.f);
    acc.w = fmaxf(acc.w + b.w, 0.f);
    ((float4*)(out + (size_t)dst * D))[lane] = acc;
}

// ---------------- pool: out[idx[i]] += val[i] * h[i] (atomic scatter) ----------------
__global__ void pool_k(const float* __restrict__ h, const int* __restrict__ idx,
                       const float* __restrict__ val, int n_src, float* __restrict__ out) {
    int i = (blockIdx.x * blockDim.x + threadIdx.x) >> 5;
    int lane = threadIdx.x & 31;
    if (i >= n_src) return;
    int c = idx[i];
    float v = val[i];
    float4 u = ((const float4*)(h + (size_t)i * D))[lane];
    float* o = out + (size_t)c * D + lane * 4;
    atomicAdd(o + 0, v * u.x);
    atomicAdd(o + 1, v * u.y);
    atomicAdd(o + 2, v * u.z);
    atomicAdd(o + 3, v * u.w);
}

// ---------------- unpool: out[i] = val[i]*h[clamp(idx[i])] + enc[i] ----------------
__global__ void unpool_k(const float* __restrict__ h, int h_rows,
                         const int* __restrict__ idx, const float* __restrict__ val,
                         const float* __restrict__ enc, int n, float* __restrict__ out) {
    int i = (blockIdx.x * blockDim.x + threadIdx.x) >> 5;
    int lane = threadIdx.x & 31;
    if (i >= n) return;
    int c = min(idx[i], h_rows - 1);
    float v = val[i];
    float4 u = ((const float4*)(h + (size_t)c * D))[lane];
    float4 e = ((const float4*)(enc + (size_t)i * D))[lane];
    float4 o = make_float4(v * u.x + e.x, v * u.y + e.y, v * u.z + e.z, v * u.w + e.w);
    ((float4*)(out + (size_t)i * D))[lane] = o;
}

// ---------------- row normalize ----------------
__global__ void normalize_k(const float* __restrict__ h, int n, float* __restrict__ out) {
    int i = (blockIdx.x * blockDim.x + threadIdx.x) >> 5;
    int lane = threadIdx.x & 31;
    if (i >= n) return;
    float4 u = ((const float4*)(h + (size_t)i * D))[lane];
    float s = u.x * u.x + u.y * u.y + u.z * u.z + u.w * u.w;
#pragma unroll
    for (int o = 16; o; o >>= 1) s += __shfl_xor_sync(0xffffffffu, s, o);
    float inv = 1.0f / fmaxf(sqrtf(s), 1e-12f);
    float4 o4 = make_float4(u.x * inv, u.y * inv, u.z * inv, u.w * inv);
    ((float4*)(out + (size_t)i * D))[lane] = o4;
}

// ---------------- host orchestration ----------------
static inline int cdiv(int a, int b) { return (a + b - 1) / b; }

static void build_csr(const int* edges, int E, int n,
                      int* deg, int* rp, int* cur, int* src, float* dis) {
    zero_int_k<<<cdiv(n, 256), 256>>>(deg, n);
    hist_k<<<cdiv(E, 256), 256>>>(edges + E, E, deg);
    scan_k<<<1, 1024>>>(deg, rp, cur, dis, n);
    scatter_k<<<cdiv(E, 256), 256>>>(edges, edges + E, E, cur, src);
}

extern "C" void kernel_launch(void* const* d_in, const int* in_sizes, int n_in,
                              void* d_out, int out_size) {
    const float* x   = (const float*)d_in[0];
    const int* e0    = (const int*)d_in[1];
    const int* e1    = (const int*)d_in[2];
    const int* e2    = (const int*)d_in[3];
    const int* C0i   = (const int*)d_in[4];
    const float* C0v = (const float*)d_in[5];
    const int* C1i   = (const int*)d_in[6];
    const float* C1v = (const float*)d_in[7];
    const float* W_enc0 = (const float*)d_in[8];
    const float* b_enc0 = (const float*)d_in[9];
    const float* W_enc1 = (const float*)d_in[10];
    const float* b_enc1 = (const float*)d_in[11];
    const float* W_enc2 = (const float*)d_in[12];
    const float* b_enc2 = (const float*)d_in[13];
    const float* W_bot  = (const float*)d_in[14];
    const float* b_bot  = (const float*)d_in[15];
    const float* W_dec0 = (const float*)d_in[16];
    const float* b_dec0 = (const float*)d_in[17];
    const float* W_dec1 = (const float*)d_in[18];
    const float* b_dec1 = (const float*)d_in[19];
    const float* W_dec2 = (const float*)d_in[20];
    const float* b_dec2 = (const float*)d_in[21];

    // resolve device-global addresses
    float *t, *enc0, *enc1, *h, *h2;
    int *deg0, *rp0, *cur0, *src0, *deg1, *rp1, *cur1, *src1, *deg2, *rp2, *cur2, *src2;
    float *dis0, *dis1, *dis2;
    cudaGetSymbolAddress((void**)&t, g_t);
    cudaGetSymbolAddress((void**)&enc0, g_enc0);
    cudaGetSymbolAddress((void**)&enc1, g_enc1);
    cudaGetSymbolAddress((void**)&h, g_h);
    cudaGetSymbolAddress((void**)&h2, g_h2);
    cudaGetSymbolAddress((void**)&deg0, g_deg0);
    cudaGetSymbolAddress((void**)&rp0, g_rp0);
    cudaGetSymbolAddress((void**)&cur0, g_cur0);
    cudaGetSymbolAddress((void**)&src0, g_src0);
    cudaGetSymbolAddress((void**)&dis0, g_dis0);
    cudaGetSymbolAddress((void**)&deg1, g_deg1);
    cudaGetSymbolAddress((void**)&rp1, g_rp1);
    cudaGetSymbolAddress((void**)&cur1, g_cur1);
    cudaGetSymbolAddress((void**)&src1, g_src1);
    cudaGetSymbolAddress((void**)&dis1, g_dis1);
    cudaGetSymbolAddress((void**)&deg2, g_deg2);
    cudaGetSymbolAddress((void**)&rp2, g_rp2);
    cudaGetSymbolAddress((void**)&cur2, g_cur2);
    cudaGetSymbolAddress((void**)&src2, g_src2);
    cudaGetSymbolAddress((void**)&dis2, g_dis2);

    // CSR for all 3 graphs
    build_csr(e0, E0, N0, deg0, rp0, cur0, src0, dis0);
    build_csr(e1, E1, N1, deg1, rp1, cur1, src1, dis1);
    build_csr(e2, E2, N2, deg2, rp2, cur2, src2, dis2);

    const int AT = 256;  // agg/pool/unpool/norm block size (8 warps)

    // ---- encoder level 0 ----
    gemm128_k<<<cdiv(N0, 64), 256>>>(x, W_enc0, t, N0);
    agg_k<<<cdiv(N0, 8), AT>>>(t, N0, rp0, src0, dis0, N0, b_enc0, enc0);
    // pool 0 -> h (N1 rows)
    zero_float_k<<<cdiv(N1 * D, 256), 256>>>(h, N1 * D);
    pool_k<<<cdiv(N0, 8), AT>>>(enc0, C0i, C0v, N0, h);
    // ---- encoder level 1 ----
    gemm128_k<<<cdiv(N1, 64), 256>>>(h, W_enc1, t, N1);
    agg_k<<<cdiv(N1, 8), AT>>>(t, N1, rp1, src1, dis1, N1, b_enc1, enc1);
    // pool 1 -> h (N2 rows)
    zero_float_k<<<cdiv(N2 * D, 256), 256>>>(h, N2 * D);
    pool_k<<<cdiv(N1, 8), AT>>>(enc1, C1i, C1v, N1, h);
    // ---- encoder level 2 -> h2 (N2) ----
    gemm128_k<<<cdiv(N2, 64), 256>>>(h, W_enc2, t, N2);
    agg_k<<<cdiv(N2, 8), AT>>>(t, N2, rp2, src2, dis2, N2, b_enc2, h2);
    // ---- bottleneck -> h (N2) ----
    gemm128_k<<<cdiv(N2, 64), 256>>>(h2, W_bot, t, N2);
    agg_k<<<cdiv(N2, 8), AT>>>(t, N2, rp2, src2, dis2, N2, b_bot, h);
    // ---- decoder l=2: unpool C1 (-> N1 rows), conv on graph2 (n=N2) ----
    unpool_k<<<cdiv(N1, 8), AT>>>(h, N2, C1i, C1v, enc1, N1, h2);
    gemm128_k<<<cdiv(N1, 64), 256>>>(h2, W_dec2, t, N1);
    agg_k<<<cdiv(N2, 8), AT>>>(t, N1, rp2, src2, dis2, N2, b_dec2, h);   // out: N2 rows
    // ---- decoder l=1: unpool C0 (clamped gather! h has N2 rows), conv graph1 (n=N1) ----
    unpool_k<<<cdiv(N0, 8), AT>>>(h, N2, C0i, C0v, enc0, N0, h2);
    gemm128_k<<<cdiv(N0, 64), 256>>>(h2, W_dec1, t, N0);
    agg_k<<<cdiv(N1, 8), AT>>>(t, N0, rp1, src1, dis1, N1, b_dec1, h);   // out: N1 rows
    // ---- decoder l=0: conv graph0 (n=N0, h has N1 rows -> clamped gather) ----
    gemm128_k<<<cdiv(N1, 64), 256>>>(h, W_dec0, t, N1);
    agg_k<<<cdiv(N0, 8), AT>>>(t, N1, rp0, src0, dis0, N0, b_dec0, h2);  // out: N0 rows
    // ---- normalize ----
    normalize_k<<<cdiv(N0, 8), AT>>>(h2, N0, (float*)d_out);
}

// round 2
// speedup vs baseline: 1.4887x; 1.4887x over previous
#include <cuda_runtime.h>
#include <cuda_bf16.h>

#define N0 50000
#define N1 12500
#define N2 3125
#define E0 800000
#define E1 200000
#define E2 50000
#define ET (E0 + E1 + E2)
#define NT (N0 + N1 + N2)
#define D 128

// tile mapping for scans: 4096 nodes per tile
#define T0 13
#define T1 4
#define T2 1
#define NB (T0 + T1 + T2)   // 18

// rp offsets (per-graph rowptr arrays, each length n+1)
#define RP0 0
#define RP1 (N0 + 1)
#define RP2 (N0 + N1 + 2)

// ---------------- scratch (device globals) ----------------
__device__ float g_t[N0 * D];
__device__ float g_enc0[N0 * D];
__device__ float g_enc1[N1 * D];
__device__ float g_h[N0 * D];
__device__ float g_h2[N0 * D];

__device__ int   g_deg[NT];
__device__ int   g_rp[NT + 3];
__device__ int   g_cur[NT];
__device__ float g_dis[NT];
__device__ int   g_src[ET];
__device__ int   g_part[32];

// ---------------- f32x2 helpers ----------------
typedef unsigned long long u64;

__device__ __forceinline__ u64 pack2(float x) {
    u64 r;
    asm("mov.b64 %0, {%1, %1};" : "=l"(r) : "f"(x));
    return r;
}
__device__ __forceinline__ void fma2(u64& d, u64 a, u64 b) {
    asm("fma.rn.f32x2 %0, %1, %2, %0;" : "+l"(d) : "l"(a), "l"(b));
}
__device__ __forceinline__ float2 unpack2(u64 v) {
    float2 r;
    asm("mov.b64 {%0, %1}, %2;" : "=f"(r.x), "=f"(r.y) : "l"(v));
    return r;
}

// ---------------- utility kernels ----------------
__global__ void zero_int_k(int* p, int n) {
    int i = blockIdx.x * blockDim.x + threadIdx.x;
    if (i < n) p[i] = 0;
}

__global__ void zero_f4_k(float4* p, int n4) {
    int i = blockIdx.x * blockDim.x + threadIdx.x;
    if (i < n4) p[i] = make_float4(0.f, 0.f, 0.f, 0.f);
}

// ---------------- CSR build: hist (all 3 graphs, int4 ILP) ----------------
__global__ void hist4_k(const int* __restrict__ e0, const int* __restrict__ e1,
                        const int* __restrict__ e2, int* __restrict__ deg) {
    int i = blockIdx.x * blockDim.x + threadIdx.x;
    int i4 = i * 4;
    if (i4 < E0) {
        int4 c = *(const int4*)(e0 + E0 + i4);
        atomicAdd(&deg[c.x], 1); atomicAdd(&deg[c.y], 1);
        atomicAdd(&deg[c.z], 1); atomicAdd(&deg[c.w], 1);
    } else if (i4 < E0 + E1) {
        int j = i4 - E0;
        int4 c = *(const int4*)(e1 + E1 + j);
        atomicAdd(&deg[N0 + c.x], 1); atomicAdd(&deg[N0 + c.y], 1);
        atomicAdd(&deg[N0 + c.z], 1); atomicAdd(&deg[N0 + c.w], 1);
    } else if (i4 < ET) {
        int j = i4 - E0 - E1;
        int4 c = *(const int4*)(e2 + E2 + j);
        atomicAdd(&deg[N0 + N1 + c.x], 1); atomicAdd(&deg[N0 + N1 + c.y], 1);
        atomicAdd(&deg[N0 + N1 + c.z], 1); atomicAdd(&deg[N0 + N1 + c.w], 1);
    }
}

// ---------------- scan phase A: per-tile sums ----------------
__device__ __forceinline__ void tile_map(int b, int& noff, int& ng, int& t, int& rpoff) {
    if (b < T0)       { noff = 0;       ng = N0; t = b;           rpoff = RP0; }
    else if (b < T0 + T1) { noff = N0;  ng = N1; t = b - T0;      rpoff = RP1; }
    else              { noff = N0 + N1; ng = N2; t = b - T0 - T1; rpoff = RP2; }
}

__global__ void scan_sum_k(const int* __restrict__ deg) {
    int noff, ng, t, rpoff;
    tile_map(blockIdx.x, noff, ng, t, rpoff);
    int tid = threadIdx.x;
    int i = t * 4096 + tid * 4;
    int s = 0;
#pragma unroll
    for (int q = 0; q < 4; q++) {
        int l = i + q;
        if (l < ng) s += deg[noff + l];
    }
#pragma unroll
    for (int o = 16; o; o >>= 1) s += __shfl_xor_sync(0xffffffffu, s, o);
    __shared__ int ws[32];
    if ((tid & 31) == 0) ws[tid >> 5] = s;
    __syncthreads();
    if (tid < 32) {
        int v = ws[tid];
#pragma unroll
        for (int o = 16; o; o >>= 1) v += __shfl_xor_sync(0xffffffffu, v, o);
        if (tid == 0) g_part[blockIdx.x] = v;
    }
}

// ---------------- scan phase B: scan tile partials per graph ----------------
__global__ void scan_mid_k(int* __restrict__ rp) {
    int g = threadIdx.x;
    if (g >= 3) return;
    const int seg0[3] = {0, T0, T0 + T1};
    const int cnt[3]  = {T0, T1, T2};
    const int ngs[3]  = {N0, N1, N2};
    const int rpo[3]  = {RP0, RP1, RP2};
    int running = 0;
    for (int t = 0; t < cnt[g]; t++) {
        int v = g_part[seg0[g] + t];
        g_part[seg0[g] + t] = running;
        running += v;
    }
    rp[rpo[g] + ngs[g]] = running;
}

// ---------------- scan phase C: per-tile scan + write rp/cur/dis ----------------
__global__ void scan_wr_k(const int* __restrict__ deg, int* __restrict__ rp,
                          int* __restrict__ cur, float* __restrict__ dis) {
    int noff, ng, t, rpoff;
    tile_map(blockIdx.x, noff, ng, t, rpoff);
    int tid = threadIdx.x;
    int lane = tid & 31, w = tid >> 5;
    int i = t * 4096 + tid * 4;
    int v[4];
    int s = 0;
#pragma unroll
    for (int q = 0; q < 4; q++) {
        int l = i + q;
        v[q] = (l < ng) ? deg[noff + l] : 0;
        s += v[q];
    }
    int incl = s;
#pragma unroll
    for (int o = 1; o < 32; o <<= 1) {
        int tv = __shfl_up_sync(0xffffffffu, incl, o);
        if (lane >= o) incl += tv;
    }
    __shared__ int ws[32];
    if (lane == 31) ws[w] = incl;
    __syncthreads();
    if (w == 0) {
        int x = ws[lane];
#pragma unroll
        for (int o = 1; o < 32; o <<= 1) {
            int tv = __shfl_up_sync(0xffffffffu, x, o);
            if (lane >= o) x += tv;
        }
        ws[lane] = x;   // inclusive scan of warp sums
    }
    __syncthreads();
    int base = g_part[blockIdx.x] + (w > 0 ? ws[w - 1] : 0) + (incl - s);
    int run = base;
#pragma unroll
    for (int q = 0; q < 4; q++) {
        int l = i + q;
        if (l < ng) {
            rp[rpoff + l] = run;
            cur[noff + l] = run;
            dis[noff + l] = rsqrtf((float)(v[q] + 1));
            run += v[q];
        }
    }
}

// ---------------- CSR scatter (all 3 graphs, int4 ILP) ----------------
__global__ void scatter4_k(const int* __restrict__ e0, const int* __restrict__ e1,
                           const int* __restrict__ e2, int* __restrict__ cur,
                           int* __restrict__ src) {
    int i = blockIdx.x * blockDim.x + threadIdx.x;
    int i4 = i * 4;
    if (i4 < E0) {
        int4 c = *(const int4*)(e0 + E0 + i4);
        int4 r = *(const int4*)(e0 + i4);
        int p;
        p = atomicAdd(&cur[c.x], 1); src[p] = r.x;
        p = atomicAdd(&cur[c.y], 1); src[p] = r.y;
        p = atomicAdd(&cur[c.z], 1); src[p] = r.z;
        p = atomicAdd(&cur[c.w], 1); src[p] = r.w;
    } else if (i4 < E0 + E1) {
        int j = i4 - E0;
        int4 c = *(const int4*)(e1 + E1 + j);
        int4 r = *(const int4*)(e1 + j);
        int p;
        p = atomicAdd(&cur[N0 + c.x], 1); src[E0 + p] = r.x;
        p = atomicAdd(&cur[N0 + c.y], 1); src[E0 + p] = r.y;
        p = atomicAdd(&cur[N0 + c.z], 1); src[E0 + p] = r.z;
        p = atomicAdd(&cur[N0 + c.w], 1); src[E0 + p] = r.w;
    } else if (i4 < ET) {
        int j = i4 - E0 - E1;
        int4 c = *(const int4*)(e2 + E2 + j);
        int4 r = *(const int4*)(e2 + j);
        int p;
        p = atomicAdd(&cur[N0 + N1 + c.x], 1); src[E0 + E1 + p] = r.x;
        p = atomicAdd(&cur[N0 + N1 + c.y], 1); src[E0 + E1 + p] = r.y;
        p = atomicAdd(&cur[N0 + N1 + c.z], 1); src[E0 + E1 + p] = r.z;
        p = atomicAdd(&cur[N0 + N1 + c.w], 1); src[E0 + E1 + p] = r.w;
    }
}

// ---------------- GEMM: C[rows x 128] = A[rows x 128] @ W[128 x 128] -------------
// Full W (64KB) + A tile (k-major) in smem; inner loop in packed fma.rn.f32x2.
template<int BM>
__global__ __launch_bounds__(256) void gemm_k(const float* __restrict__ A,
                                              const float* __restrict__ W,
                                              float* __restrict__ C, int rows) {
    constexpr int TM = BM / 16;
    constexpr int AST = BM + 4;        // padded row stride of k-major A tile
    extern __shared__ float sm[];
    float* Ws = sm;                    // [128][128]
    float* As = sm + 128 * 128;        // [128 k][AST]
    int tid = threadIdx.x;
    int row0 = blockIdx.x * BM;

    // load W (coalesced float4)
#pragma unroll
    for (int j = 0; j < 16; j++) {
        int idx = tid + j * 256;
        ((float4*)Ws)[idx] = ((const float4*)W)[idx];
    }
    // load A transposed to k-major: lane pattern 8 rows x 4 float4-cols
    {
        int w = tid >> 5, l = tid & 31;
        int rsub = l >> 2, c4l = l & 3;
#pragma unroll
        for (int j = 0; j < BM / 8; j++) {
            int m = j * 8 + w;                 // [0, BM)
            int rblk = m % (BM / 8);
            int cblk = m / (BM / 8);           // 0..7
            int r = rblk * 8 + rsub;
            int c4 = cblk * 4 + c4l;           // 0..31
            float4 v = make_float4(0.f, 0.f, 0.f, 0.f);
            if (row0 + r < rows)
                v = *(const float4*)(A + (size_t)(row0 + r) * D + c4 * 4);
            int kb = c4 * 4;
            As[(kb + 0) * AST + r] = v.x;
            As[(kb + 1) * AST + r] = v.y;
            As[(kb + 2) * AST + r] = v.z;
            As[(kb + 3) * AST + r] = v.w;
        }
    }
    __syncthreads();

    int tr = tid >> 4, tc = tid & 15;
    u64 acc[TM][4] = {};
#pragma unroll 4
    for (int kk = 0; kk < 128; kk++) {
        const ulonglong2* wp = (const ulonglong2*)(Ws + kk * 128 + tc * 8);
        ulonglong2 q0 = wp[0];
        ulonglong2 q1 = wp[1];
        float a[TM];
        const float* ap = As + kk * AST + tr * TM;
        if (TM == 8) {
            float4 a0 = *(const float4*)ap;
            float4 a1 = *(const float4*)(ap + 4);
            a[0] = a0.x; a[1] = a0.y; a[2] = a0.z; a[3] = a0.w;
            a[4] = a1.x; a[5] = a1.y; a[6] = a1.z; a[7] = a1.w;
        } else {
            float2 a0 = *(const float2*)ap;
            a[0] = a0.x; a[1] = a0.y;
        }
#pragma unroll
        for (int i = 0; i < TM; i++) {
            u64 av = pack2(a[i]);
            fma2(acc[i][0], av, q0.x);
            fma2(acc[i][1], av, q0.y);
            fma2(acc[i][2], av, q1.x);
            fma2(acc[i][3], av, q1.y);
        }
    }
#pragma unroll
    for (int i = 0; i < TM; i++) {
        int gr = row0 + tr * TM + i;
        if (gr < rows) {
            float2 p0 = unpack2(acc[i][0]), p1 = unpack2(acc[i][1]);
            float2 p2 = unpack2(acc[i][2]), p3 = unpack2(acc[i][3]);
            *(float4*)(C + (size_t)gr * D + tc * 8)     = make_float4(p0.x, p0.y, p1.x, p1.y);
            *(float4*)(C + (size_t)gr * D + tc * 8 + 4) = make_float4(p2.x, p2.y, p3.x, p3.y);
        }
    }
}

// ---------------- aggregation (warp per dst; optional fused row-normalize) -------
template<bool NORM>
__global__ void agg_k(const float* __restrict__ t, int h_rows,
                      const int* __restrict__ rp, const int* __restrict__ src,
                      const float* __restrict__ dis, int n,
                      const float* __restrict__ bias, float* __restrict__ out) {
    int warp = (blockIdx.x * blockDim.x + threadIdx.x) >> 5;
    int lane = threadIdx.x & 31;
    if (warp >= n) return;
    int dst = warp;
    float dd = dis[dst];
    int hc = h_rows - 1;
    float4 v = ((const float4*)(t + (size_t)min(dst, hc) * D))[lane];
    float w0 = dd * dd;
    float4 a1 = make_float4(w0 * v.x, w0 * v.y, w0 * v.z, w0 * v.w);
    float4 a2 = make_float4(0.f, 0.f, 0.f, 0.f);
    int e = rp[dst], end = rp[dst + 1];
    for (; e + 2 <= end; e += 2) {
        int s0 = src[e], s1 = src[e + 1];
        float q0 = dis[s0] * dd, q1 = dis[s1] * dd;
        float4 u0 = ((const float4*)(t + (size_t)min(s0, hc) * D))[lane];
        float4 u1 = ((const float4*)(t + (size_t)min(s1, hc) * D))[lane];
        a1.x += q0 * u0.x; a1.y += q0 * u0.y; a1.z += q0 * u0.z; a1.w += q0 * u0.w;
        a2.x += q1 * u1.x; a2.y += q1 * u1.y; a2.z += q1 * u1.z; a2.w += q1 * u1.w;
    }
    if (e < end) {
        int s0 = src[e];
        float q0 = dis[s0] * dd;
        float4 u0 = ((const float4*)(t + (size_t)min(s0, hc) * D))[lane];
        a1.x += q0 * u0.x; a1.y += q0 * u0.y; a1.z += q0 * u0.z; a1.w += q0 * u0.w;
    }
    float4 b = ((const float4*)bias)[lane];
    float4 r;
    r.x = fmaxf(a1.x + a2.x + b.x, 0.f);
    r.y = fmaxf(a1.y + a2.y + b.y, 0.f);
    r.z = fmaxf(a1.z + a2.z + b.z, 0.f);
    r.w = fmaxf(a1.w + a2.w + b.w, 0.f);
    if (NORM) {
        float s = r.x * r.x + r.y * r.y + r.z * r.z + r.w * r.w;
#pragma unroll
        for (int o = 16; o; o >>= 1) s += __shfl_xor_sync(0xffffffffu, s, o);
        float inv = 1.0f / fmaxf(sqrtf(s), 1e-12f);
        r.x *= inv; r.y *= inv; r.z *= inv; r.w *= inv;
    }
    ((float4*)(out + (size_t)dst * D))[lane] = r;
}

// ---------------- pool: out[idx[i]] += val[i] * h[i] ----------------
__global__ void pool_k(const float* __restrict__ h, const int* __restrict__ idx,
                       const float* __restrict__ val, int n_src, float* __restrict__ out) {
    int i = (blockIdx.x * blockDim.x + threadIdx.x) >> 5;
    int lane = threadIdx.x & 31;
    if (i >= n_src) return;
    int c = idx[i];
    float v = val[i];
    float4 u = ((const float4*)(h + (size_t)i * D))[lane];
    float* o = out + (size_t)c * D + lane * 4;
    atomicAdd(o + 0, v * u.x);
    atomicAdd(o + 1, v * u.y);
    atomicAdd(o + 2, v * u.z);
    atomicAdd(o + 3, v * u.w);
}

// ---------------- unpool: out[i] = val[i]*h[clamp(idx[i])] + enc[i] ----------------
__global__ void unpool_k(const float* __restrict__ h, int h_rows,
                         const int* __restrict__ idx, const float* __restrict__ val,
                         const float* __restrict__ enc, int n, float* __restrict__ out) {
    int i = (blockIdx.x * blockDim.x + threadIdx.x) >> 5;
    int lane = threadIdx.x & 31;
    if (i >= n) return;
    int c = min(idx[i], h_rows - 1);
    float v = val[i];
    float4 u = ((const float4*)(h + (size_t)c * D))[lane];
    float4 e = ((const float4*)(enc + (size_t)i * D))[lane];
    ((float4*)(out + (size_t)i * D))[lane] =
        make_float4(v * u.x + e.x, v * u.y + e.y, v * u.z + e.z, v * u.w + e.w);
}

// ---------------- host orchestration ----------------
static inline int cdiv(int a, int b) { return (a + b - 1) / b; }

extern "C" void kernel_launch(void* const* d_in, const int* in_sizes, int n_in,
                              void* d_out, int out_size) {
    const float* x   = (const float*)d_in[0];
    const int* e0    = (const int*)d_in[1];
    const int* e1    = (const int*)d_in[2];
    const int* e2    = (const int*)d_in[3];
    const int* C0i   = (const int*)d_in[4];
    const float* C0v = (const float*)d_in[5];
    const int* C1i   = (const int*)d_in[6];
    const float* C1v = (const float*)d_in[7];
    const float* W_enc0 = (const float*)d_in[8];
    const float* b_enc0 = (const float*)d_in[9];
    const float* W_enc1 = (const float*)d_in[10];
    const float* b_enc1 = (const float*)d_in[11];
    const float* W_enc2 = (const float*)d_in[12];
    const float* b_enc2 = (const float*)d_in[13];
    const float* W_bot  = (const float*)d_in[14];
    const float* b_bot  = (const float*)d_in[15];
    const float* W_dec0 = (const float*)d_in[16];
    const float* b_dec0 = (const float*)d_in[17];
    const float* W_dec1 = (const float*)d_in[18];
    const float* b_dec1 = (const float*)d_in[19];
    const float* W_dec2 = (const float*)d_in[20];
    const float* b_dec2 = (const float*)d_in[21];

    float *t, *enc0, *enc1, *h, *h2, *dis;
    int *deg, *rp, *cur, *src;
    cudaGetSymbolAddress((void**)&t, g_t);
    cudaGetSymbolAddress((void**)&enc0, g_enc0);
    cudaGetSymbolAddress((void**)&enc1, g_enc1);
    cudaGetSymbolAddress((void**)&h, g_h);
    cudaGetSymbolAddress((void**)&h2, g_h2);
    cudaGetSymbolAddress((void**)&deg, g_deg);
    cudaGetSymbolAddress((void**)&rp, g_rp);
    cudaGetSymbolAddress((void**)&cur, g_cur);
    cudaGetSymbolAddress((void**)&src, g_src);
    cudaGetSymbolAddress((void**)&dis, g_dis);

    const int S128 = (128 * 128 + 128 * (128 + 4)) * (int)sizeof(float);  // 133120
    const int S32  = (128 * 128 + 128 * (32 + 4)) * (int)sizeof(float);   // 83968
    cudaFuncSetAttribute(gemm_k<128>, cudaFuncAttributeMaxDynamicSharedMemorySize, S128);
    cudaFuncSetAttribute(gemm_k<32>,  cudaFuncAttributeMaxDynamicSharedMemorySize, S32);

    // ---- CSR build (all 3 graphs) ----
    zero_int_k<<<cdiv(NT, 1024), 1024>>>(deg, NT);
    hist4_k<<<cdiv(ET / 4, 256), 256>>>(e0, e1, e2, deg);
    scan_sum_k<<<NB, 1024>>>(deg);
    scan_mid_k<<<1, 32>>>(rp);
    scan_wr_k<<<NB, 1024>>>(deg, rp, cur, dis);
    scatter4_k<<<cdiv(ET / 4, 256), 256>>>(e0, e1, e2, cur, src);

    const int AT = 256;
    const int* rp0 = rp + RP0; const int* src0 = src;           const float* dis0 = dis;
    const int* rp1 = rp + RP1; const int* src1 = src + E0;      const float* dis1 = dis + N0;
    const int* rp2 = rp + RP2; const int* src2 = src + E0 + E1; const float* dis2 = dis + N0 + N1;

    // ---- encoder level 0 ----
    gemm_k<128><<<cdiv(N0, 128), 256, S128>>>(x, W_enc0, t, N0);
    agg_k<false><<<cdiv(N0, 8), AT>>>(t, N0, rp0, src0, dis0, N0, b_enc0, enc0);
    zero_f4_k<<<cdiv(N1 * D / 4, 256), 256>>>((float4*)h, N1 * D / 4);
    pool_k<<<cdiv(N0, 8), AT>>>(enc0, C0i, C0v, N0, h);
    // ---- encoder level 1 ----
    gemm_k<128><<<cdiv(N1, 128), 256, S128>>>(h, W_enc1, t, N1);
    agg_k<false><<<cdiv(N1, 8), AT>>>(t, N1, rp1, src1, dis1, N1, b_enc1, enc1);
    zero_f4_k<<<cdiv(N2 * D / 4, 256), 256>>>((float4*)h, N2 * D / 4);
    pool_k<<<cdiv(N1, 8), AT>>>(enc1, C1i, C1v, N1, h);
    // ---- encoder level 2 ----
    gemm_k<32><<<cdiv(N2, 32), 256, S32>>>(h, W_enc2, t, N2);
    agg_k<false><<<cdiv(N2, 8), AT>>>(t, N2, rp2, src2, dis2, N2, b_enc2, h2);
    // ---- bottleneck ----
    gemm_k<32><<<cdiv(N2, 32), 256, S32>>>(h2, W_bot, t, N2);
    agg_k<false><<<cdiv(N2, 8), AT>>>(t, N2, rp2, src2, dis2, N2, b_bot, h);
    // ---- decoder l=2 ----
    unpool_k<<<cdiv(N1, 8), AT>>>(h, N2, C1i, C1v, enc1, N1, h2);
    gemm_k<128><<<cdiv(N1, 128), 256, S128>>>(h2, W_dec2, t, N1);
    agg_k<false><<<cdiv(N2, 8), AT>>>(t, N1, rp2, src2, dis2, N2, b_dec2, h);
    // ---- decoder l=1 (clamped gathers, matching JAX OOB semantics) ----
    unpool_k<<<cdiv(N0, 8), AT>>>(h, N2, C0i, C0v, enc0, N0, h2);
    gemm_k<128><<<cdiv(N0, 128), 256, S128>>>(h2, W_dec1, t, N0);
    agg_k<false><<<cdiv(N1, 8), AT>>>(t, N0, rp1, src1, dis1, N1, b_dec1, h);
    // ---- decoder l=0 + fused normalize ----
    gemm_k<128><<<cdiv(N1, 128), 256, S128>>>(h, W_dec0, t, N1);
    agg_k<true><<<cdiv(N0, 8), AT>>>(t, N1, rp0, src0, dis0, N0, b_dec0, (float*)d_out);
}

// round 3
// speedup vs baseline: 1.6536x; 1.1108x over previous
#include <cuda_runtime.h>
#include <cuda_bf16.h>

#define N0 50000
#define N1 12500
#define N2 3125
#define E0 800000
#define E1 200000
#define E2 50000
#define ET (E0 + E1 + E2)
#define NT (N0 + N1 + N2)
#define D 128

// tile mapping for scan: 4096 nodes per tile
#define T0 13
#define T1 4
#define T2 1
#define NB (T0 + T1 + T2)   // 18

// rp offsets (per-graph rowptr arrays, each length n+1)
#define RP0 0
#define RP1 (N0 + 1)
#define RP2 (N0 + N1 + 2)

// ---------------- scratch (device globals) ----------------
__device__ float g_t[N0 * D];
__device__ float g_enc0[N0 * D];
__device__ float g_enc1[N1 * D];
__device__ float g_h[N0 * D];
__device__ float g_h2[N0 * D];

__device__ int   g_deg[NT];
__device__ int   g_rp[NT + 3];
__device__ int   g_cur[NT];
__device__ float g_dis[NT];
__device__ int   g_src[ET];

// ---------------- f32x2 helpers ----------------
typedef unsigned long long u64;

__device__ __forceinline__ u64 pack2(float x) {
    u64 r;
    asm("mov.b64 %0, {%1, %1};" : "=l"(r) : "f"(x));
    return r;
}
__device__ __forceinline__ void fma2(u64& d, u64 a, u64 b) {
    asm("fma.rn.f32x2 %0, %1, %2, %0;" : "+l"(d) : "l"(a), "l"(b));
}
__device__ __forceinline__ float2 unpack2(u64 v) {
    float2 r;
    asm("mov.b64 {%0, %1}, %2;" : "=f"(r.x), "=f"(r.y) : "l"(v));
    return r;
}

// ---------------- utility kernels ----------------
// zero deg[NT] and h[0 .. N1*D) in one kernel
__global__ void zero_init_k(int* deg, float4* h) {
    int i = blockIdx.x * blockDim.x + threadIdx.x;
    if (i < NT) deg[i] = 0;
    int nh = N1 * D / 4;
    for (int j = i; j < nh; j += gridDim.x * blockDim.x)
        h[j] = make_float4(0.f, 0.f, 0.f, 0.f);
}

__global__ void zero_f4_k(float4* p, int n4) {
    int i = blockIdx.x * blockDim.x + threadIdx.x;
    if (i < n4) p[i] = make_float4(0.f, 0.f, 0.f, 0.f);
}

// ---------------- CSR build: hist (all 3 graphs, int4 ILP) ----------------
__global__ void hist4_k(const int* __restrict__ e0, const int* __restrict__ e1,
                        const int* __restrict__ e2, int* __restrict__ deg) {
    int i = blockIdx.x * blockDim.x + threadIdx.x;
    int i4 = i * 4;
    if (i4 < E0) {
        int4 c = *(const int4*)(e0 + E0 + i4);
        atomicAdd(&deg[c.x], 1); atomicAdd(&deg[c.y], 1);
        atomicAdd(&deg[c.z], 1); atomicAdd(&deg[c.w], 1);
    } else if (i4 < E0 + E1) {
        int j = i4 - E0;
        int4 c = *(const int4*)(e1 + E1 + j);
        atomicAdd(&deg[N0 + c.x], 1); atomicAdd(&deg[N0 + c.y], 1);
        atomicAdd(&deg[N0 + c.z], 1); atomicAdd(&deg[N0 + c.w], 1);
    } else if (i4 < ET) {
        int j = i4 - E0 - E1;
        int4 c = *(const int4*)(e2 + E2 + j);
        atomicAdd(&deg[N0 + N1 + c.x], 1); atomicAdd(&deg[N0 + N1 + c.y], 1);
        atomicAdd(&deg[N0 + N1 + c.z], 1); atomicAdd(&deg[N0 + N1 + c.w], 1);
    }
}

__device__ __forceinline__ void tile_map(int b, int& noff, int& ng, int& t, int& rpoff) {
    if (b < T0)           { noff = 0;       ng = N0; t = b;           rpoff = RP0; }
    else if (b < T0 + T1) { noff = N0;      ng = N1; t = b - T0;      rpoff = RP1; }
    else                  { noff = N0 + N1; ng = N2; t = b - T0 - T1; rpoff = RP2; }
}

// ---------------- fused scan: each block redundantly sums preceding tiles ----------
__global__ void scan_fused_k(const int* __restrict__ deg, int* __restrict__ rp,
                             int* __restrict__ cur, float* __restrict__ dis) {
    int noff, ng, t, rpoff;
    tile_map(blockIdx.x, noff, ng, t, rpoff);
    int tid = threadIdx.x;
    int lane = tid & 31, w = tid >> 5;
    __shared__ int ws[32];
    __shared__ int s_pre;

    // --- prefix over preceding tiles of this graph: sum deg[noff .. noff + t*4096) ---
    {
        int lim = t * 4096;
        int s = 0;
        for (int i = tid * 4; i < lim; i += 4096) {
            // lim is a multiple of 4096 and of 4; vectorized read
            int4 v = *(const int4*)(deg + noff + i);
            s += v.x + v.y + v.z + v.w;
        }
#pragma unroll
        for (int o = 16; o; o >>= 1) s += __shfl_xor_sync(0xffffffffu, s, o);
        if (lane == 0) ws[w] = s;
        __syncthreads();
        if (w == 0) {
            int v = (lane < 32) ? ws[lane] : 0;
#pragma unroll
            for (int o = 16; o; o >>= 1) v += __shfl_xor_sync(0xffffffffu, v, o);
            if (lane == 0) s_pre = v;
        }
        __syncthreads();
    }

    // --- scan own tile ---
    int i = t * 4096 + tid * 4;
    int v[4];
    int s = 0;
#pragma unroll
    for (int q = 0; q < 4; q++) {
        int l = i + q;
        v[q] = (l < ng) ? deg[noff + l] : 0;
        s += v[q];
    }
    int incl = s;
#pragma unroll
    for (int o = 1; o < 32; o <<= 1) {
        int tv = __shfl_up_sync(0xffffffffu, incl, o);
        if (lane >= o) incl += tv;
    }
    __syncthreads();  // reuse ws
    if (lane == 31) ws[w] = incl;
    __syncthreads();
    if (w == 0) {
        int x = ws[lane];
#pragma unroll
        for (int o = 1; o < 32; o <<= 1) {
            int tv = __shfl_up_sync(0xffffffffu, x, o);
            if (lane >= o) x += tv;
        }
        ws[lane] = x;   // inclusive scan of warp sums
    }
    __syncthreads();
    int base = s_pre + (w > 0 ? ws[w - 1] : 0) + (incl - s);
    int run = base;
#pragma unroll
    for (int q = 0; q < 4; q++) {
        int l = i + q;
        if (l < ng) {
            rp[rpoff + l] = run;
            cur[noff + l] = run;
            dis[noff + l] = rsqrtf((float)(v[q] + 1));
            run += v[q];
        }
    }
    // last tile of each graph writes rp[ng]
    bool last = (t == ((ng + 4095) / 4096) - 1);
    if (last && tid == 1023) rp[rpoff + ng] = s_pre + ws[31];
}

// ---------------- CSR scatter (all 3 graphs, int4 ILP) ----------------
__global__ void scatter4_k(const int* __restrict__ e0, const int* __restrict__ e1,
                           const int* __restrict__ e2, int* __restrict__ cur,
                           int* __restrict__ src) {
    int i = blockIdx.x * blockDim.x + threadIdx.x;
    int i4 = i * 4;
    if (i4 < E0) {
        int4 c = *(const int4*)(e0 + E0 + i4);
        int4 r = *(const int4*)(e0 + i4);
        int p;
        p = atomicAdd(&cur[c.x], 1); src[p] = r.x;
        p = atomicAdd(&cur[c.y], 1); src[p] = r.y;
        p = atomicAdd(&cur[c.z], 1); src[p] = r.z;
        p = atomicAdd(&cur[c.w], 1); src[p] = r.w;
    } else if (i4 < E0 + E1) {
        int j = i4 - E0;
        int4 c = *(const int4*)(e1 + E1 + j);
        int4 r = *(const int4*)(e1 + j);
        int p;
        p = atomicAdd(&cur[N0 + c.x], 1); src[E0 + p] = r.x;
        p = atomicAdd(&cur[N0 + c.y], 1); src[E0 + p] = r.y;
        p = atomicAdd(&cur[N0 + c.z], 1); src[E0 + p] = r.z;
        p = atomicAdd(&cur[N0 + c.w], 1); src[E0 + p] = r.w;
    } else if (i4 < ET) {
        int j = i4 - E0 - E1;
        int4 c = *(const int4*)(e2 + E2 + j);
        int4 r = *(const int4*)(e2 + j);
        int p;
        p = atomicAdd(&cur[N0 + N1 + c.x], 1); src[E0 + E1 + p] = r.x;
        p = atomicAdd(&cur[N0 + N1 + c.y], 1); src[E0 + E1 + p] = r.y;
        p = atomicAdd(&cur[N0 + N1 + c.z], 1); src[E0 + E1 + p] = r.z;
        p = atomicAdd(&cur[N0 + N1 + c.w], 1); src[E0 + E1 + p] = r.w;
    }
}

// ---------------- GEMM: C[rows x 128] = A[rows x 128] @ W[128 x 128] -------------
// Full W (64KB) + A tile (k-major) in smem; inner loop in packed fma.rn.f32x2.
// GATHER: A row r = val[r] * hsrc[clamp(idx[r])] + enc[r]  (fused unpool)
template<int BM, bool GATHER>
__global__ __launch_bounds__(256) void gemm_k(const float* __restrict__ A,
                                              const float* __restrict__ W,
                                              float* __restrict__ C, int rows,
                                              const float* __restrict__ hsrc, int h_rows,
                                              const int* __restrict__ idx,
                                              const float* __restrict__ val,
                                              const float* __restrict__ enc) {
    constexpr int TM = BM / 16;
    constexpr int AST = BM + 4;        // padded row stride of k-major A tile
    extern __shared__ float sm[];
    float* Ws = sm;                    // [128][128]
    float* As = sm + 128 * 128;        // [128 k][AST]
    int tid = threadIdx.x;
    int row0 = blockIdx.x * BM;

    // load W (coalesced float4)
#pragma unroll
    for (int j = 0; j < 16; j++) {
        int idxw = tid + j * 256;
        ((float4*)Ws)[idxw] = ((const float4*)W)[idxw];
    }
    // load A transposed to k-major
    {
        int w = tid >> 5, l = tid & 31;
        int rsub = l >> 2, c4l = l & 3;
#pragma unroll
        for (int j = 0; j < BM / 8; j++) {
            int m = j * 8 + w;
            int rblk = m % (BM / 8);
            int cblk = m / (BM / 8);
            int r = rblk * 8 + rsub;
            int c4 = cblk * 4 + c4l;
            float4 v = make_float4(0.f, 0.f, 0.f, 0.f);
            int gr = row0 + r;
            if (gr < rows) {
                if (GATHER) {
                    int c = min(idx[gr], h_rows - 1);
                    float vv = val[gr];
                    float4 u = *(const float4*)(hsrc + (size_t)c * D + c4 * 4);
                    float4 e = *(const float4*)(enc + (size_t)gr * D + c4 * 4);
                    v = make_float4(vv * u.x + e.x, vv * u.y + e.y,
                                    vv * u.z + e.z, vv * u.w + e.w);
                } else {
                    v = *(const float4*)(A + (size_t)gr * D + c4 * 4);
                }
            }
            int kb = c4 * 4;
            As[(kb + 0) * AST + r] = v.x;
            As[(kb + 1) * AST + r] = v.y;
            As[(kb + 2) * AST + r] = v.z;
            As[(kb + 3) * AST + r] = v.w;
        }
    }
    __syncthreads();

    int tr = tid >> 4, tc = tid & 15;
    u64 acc[TM][4] = {};
#pragma unroll 4
    for (int kk = 0; kk < 128; kk++) {
        const ulonglong2* wp = (const ulonglong2*)(Ws + kk * 128 + tc * 8);
        ulonglong2 q0 = wp[0];
        ulonglong2 q1 = wp[1];
        float a[TM];
        const float* ap = As + kk * AST + tr * TM;
        if (TM == 8) {
            float4 a0 = *(const float4*)ap;
            float4 a1 = *(const float4*)(ap + 4);
            a[0] = a0.x; a[1] = a0.y; a[2] = a0.z; a[3] = a0.w;
            a[4] = a1.x; a[5] = a1.y; a[6] = a1.z; a[7] = a1.w;
        } else {
            float2 a0 = *(const float2*)ap;
            a[0] = a0.x; a[1] = a0.y;
        }
#pragma unroll
        for (int i = 0; i < TM; i++) {
            u64 av = pack2(a[i]);
            fma2(acc[i][0], av, q0.x);
            fma2(acc[i][1], av, q0.y);
            fma2(acc[i][2], av, q1.x);
            fma2(acc[i][3], av, q1.y);
        }
    }
#pragma unroll
    for (int i = 0; i < TM; i++) {
        int gr = row0 + tr * TM + i;
        if (gr < rows) {
            float2 p0 = unpack2(acc[i][0]), p1 = unpack2(acc[i][1]);
            float2 p2 = unpack2(acc[i][2]), p3 = unpack2(acc[i][3]);
            *(float4*)(C + (size_t)gr * D + tc * 8)     = make_float4(p0.x, p0.y, p1.x, p1.y);
            *(float4*)(C + (size_t)gr * D + tc * 8 + 4) = make_float4(p2.x, p2.y, p3.x, p3.y);
        }
    }
}

// ---------------- aggregation (warp per dst; unroll 4; optional fused pool/norm) ---
template<int MODE>   // 0 = plain, 1 = fused pool scatter, 2 = fused normalize
__global__ void agg_k(const float* __restrict__ t, int h_rows,
                      const int* __restrict__ rp, const int* __restrict__ src,
                      const float* __restrict__ dis, int n,
                      const float* __restrict__ bias, float* __restrict__ out,
                      const int* __restrict__ pidx, const float* __restrict__ pval,
                      float* __restrict__ pout) {
    int warp = (blockIdx.x * blockDim.x + threadIdx.x) >> 5;
    int lane = threadIdx.x & 31;
    if (warp >= n) return;
    int dst = warp;
    float dd = dis[dst];
    int hc = h_rows - 1;
    float4 v = ((const float4*)(t + (size_t)min(dst, hc) * D))[lane];
    float w0 = dd * dd;
    float4 a1 = make_float4(w0 * v.x, w0 * v.y, w0 * v.z, w0 * v.w);
    float4 a2 = make_float4(0.f, 0.f, 0.f, 0.f);
    float4 a3 = make_float4(0.f, 0.f, 0.f, 0.f);
    float4 a4 = make_float4(0.f, 0.f, 0.f, 0.f);
    int e = rp[dst], end = rp[dst + 1];
    for (; e + 4 <= end; e += 4) {
        int s0 = src[e], s1 = src[e + 1], s2 = src[e + 2], s3 = src[e + 3];
        float q0 = dis[s0] * dd, q1 = dis[s1] * dd;
        float q2 = dis[s2] * dd, q3 = dis[s3] * dd;
        float4 u0 = ((const float4*)(t + (size_t)min(s0, hc) * D))[lane];
        float4 u1 = ((const float4*)(t + (size_t)min(s1, hc) * D))[lane];
        float4 u2 = ((const float4*)(t + (size_t)min(s2, hc) * D))[lane];
        float4 u3 = ((const float4*)(t + (size_t)min(s3, hc) * D))[lane];
        a1.x += q0 * u0.x; a1.y += q0 * u0.y; a1.z += q0 * u0.z; a1.w += q0 * u0.w;
        a2.x += q1 * u1.x; a2.y += q1 * u1.y; a2.z += q1 * u1.z; a2.w += q1 * u1.w;
        a3.x += q2 * u2.x; a3.y += q2 * u2.y; a3.z += q2 * u2.z; a3.w += q2 * u2.w;
        a4.x += q3 * u3.x; a4.y += q3 * u3.y; a4.z += q3 * u3.z; a4.w += q3 * u3.w;
    }
    for (; e < end; e++) {
        int s0 = src[e];
        float q0 = dis[s0] * dd;
        float4 u0 = ((const float4*)(t + (size_t)min(s0, hc) * D))[lane];
        a1.x += q0 * u0.x; a1.y += q0 * u0.y; a1.z += q0 * u0.z; a1.w += q0 * u0.w;
    }
    float4 b = ((const float4*)bias)[lane];
    float4 r;
    r.x = fmaxf(a1.x + a2.x + a3.x + a4.x + b.x, 0.f);
    r.y = fmaxf(a1.y + a2.y + a3.y + a4.y + b.y, 0.f);
    r.z = fmaxf(a1.z + a2.z + a3.z + a4.z + b.z, 0.f);
    r.w = fmaxf(a1.w + a2.w + a3.w + a4.w + b.w, 0.f);
    if (MODE == 2) {
        float s = r.x * r.x + r.y * r.y + r.z * r.z + r.w * r.w;
#pragma unroll
        for (int o = 16; o; o >>= 1) s += __shfl_xor_sync(0xffffffffu, s, o);
        float inv = 1.0f / fmaxf(sqrtf(s), 1e-12f);
        r.x *= inv; r.y *= inv; r.z *= inv; r.w *= inv;
    }
    ((float4*)(out + (size_t)dst * D))[lane] = r;
    if (MODE == 1) {
        int c = pidx[dst];
        float pv = pval[dst];
        float* o = pout + (size_t)c * D + lane * 4;
        atomicAdd(o + 0, pv * r.x);
        atomicAdd(o + 1, pv * r.y);
        atomicAdd(o + 2, pv * r.z);
        atomicAdd(o + 3, pv * r.w);
    }
}

// ---------------- host orchestration ----------------
static inline int cdiv(int a, int b) { return (a + b - 1) / b; }

extern "C" void kernel_launch(void* const* d_in, const int* in_sizes, int n_in,
                              void* d_out, int out_size) {
    const float* x   = (const float*)d_in[0];
    const int* e0    = (const int*)d_in[1];
    const int* e1    = (const int*)d_in[2];
    const int* e2    = (const int*)d_in[3];
    const int* C0i   = (const int*)d_in[4];
    const float* C0v = (const float*)d_in[5];
    const int* C1i   = (const int*)d_in[6];
    const float* C1v = (const float*)d_in[7];
    const float* W_enc0 = (const float*)d_in[8];
    const float* b_enc0 = (const float*)d_in[9];
    const float* W_enc1 = (const float*)d_in[10];
    const float* b_enc1 = (const float*)d_in[11];
    const float* W_enc2 = (const float*)d_in[12];
    const float* b_enc2 = (const float*)d_in[13];
    const float* W_bot  = (const float*)d_in[14];
    const float* b_bot  = (const float*)d_in[15];
    const float* W_dec0 = (const float*)d_in[16];
    const float* b_dec0 = (const float*)d_in[17];
    const float* W_dec1 = (const float*)d_in[18];
    const float* b_dec1 = (const float*)d_in[19];
    const float* W_dec2 = (const float*)d_in[20];
    const float* b_dec2 = (const float*)d_in[21];

    float *t, *enc0, *enc1, *h, *h2, *dis;
    int *deg, *rp, *cur, *src;
    cudaGetSymbolAddress((void**)&t, g_t);
    cudaGetSymbolAddress((void**)&enc0, g_enc0);
    cudaGetSymbolAddress((void**)&enc1, g_enc1);
    cudaGetSymbolAddress((void**)&h, g_h);
    cudaGetSymbolAddress((void**)&h2, g_h2);
    cudaGetSymbolAddress((void**)&deg, g_deg);
    cudaGetSymbolAddress((void**)&rp, g_rp);
    cudaGetSymbolAddress((void**)&cur, g_cur);
    cudaGetSymbolAddress((void**)&src, g_src);
    cudaGetSymbolAddress((void**)&dis, g_dis);

    const int S128 = (128 * 128 + 128 * (128 + 4)) * (int)sizeof(float);
    const int S32  = (128 * 128 + 128 * (32 + 4)) * (int)sizeof(float);
    cudaFuncSetAttribute((const void*)gemm_k<128, false>, cudaFuncAttributeMaxDynamicSharedMemorySize, S128);
    cudaFuncSetAttribute((const void*)gemm_k<128, true>,  cudaFuncAttributeMaxDynamicSharedMemorySize, S128);
    cudaFuncSetAttribute((const void*)gemm_k<32, false>,  cudaFuncAttributeMaxDynamicSharedMemorySize, S32);

    const int* rp0 = rp + RP0; const int* src0 = src;           const float* dis0 = dis;
    const int* rp1 = rp + RP1; const int* src1 = src + E0;      const float* dis1 = dis + N0;
    const int* rp2 = rp + RP2; const int* src2 = src + E0 + E1; const float* dis2 = dis + N0 + N1;

    const int AT = 256;

    // ---- CSR build (all 3 graphs) + zero h(N1 rows) ----
    zero_init_k<<<cdiv(NT, 1024), 1024>>>(deg, (float4*)h);
    hist4_k<<<cdiv(ET / 4, 256), 256>>>(e0, e1, e2, deg);
    scan_fused_k<<<NB, 1024>>>(deg, rp, cur, dis);
    scatter4_k<<<cdiv(ET / 4, 256), 256>>>(e0, e1, e2, cur, src);

    // ---- encoder level 0 (agg fuses pool0 -> h) ----
    gemm_k<128, false><<<cdiv(N0, 128), 256, S128>>>(x, W_enc0, t, N0, nullptr, 0, nullptr, nullptr, nullptr);
    agg_k<1><<<cdiv(N0, 8), AT>>>(t, N0, rp0, src0, dis0, N0, b_enc0, enc0, C0i, C0v, h);
    // ---- encoder level 1 (agg fuses pool1 -> h, re-zeroed after gemm read) ----
    gemm_k<128, false><<<cdiv(N1, 128), 256, S128>>>(h, W_enc1, t, N1, nullptr, 0, nullptr, nullptr, nullptr);
    zero_f4_k<<<cdiv(N2 * D / 4, 256), 256>>>((float4*)h, N2 * D / 4);
    agg_k<1><<<cdiv(N1, 8), AT>>>(t, N1, rp1, src1, dis1, N1, b_enc1, enc1, C1i, C1v, h);
    // ---- encoder level 2 ----
    gemm_k<32, false><<<cdiv(N2, 32), 256, S32>>>(h, W_enc2, t, N2, nullptr, 0, nullptr, nullptr, nullptr);
    agg_k<0><<<cdiv(N2, 8), AT>>>(t, N2, rp2, src2, dis2, N2, b_enc2, h2, nullptr, nullptr, nullptr);
    // ---- bottleneck ----
    gemm_k<32, false><<<cdiv(N2, 32), 256, S32>>>(h2, W_bot, t, N2, nullptr, 0, nullptr, nullptr, nullptr);
    agg_k<0><<<cdiv(N2, 8), AT>>>(t, N2, rp2, src2, dis2, N2, b_bot, h, nullptr, nullptr, nullptr);
    // ---- decoder l=2: gemm fuses unpool C1 (h has N2 rows) ----
    gemm_k<128, true><<<cdiv(N1, 128), 256, S128>>>(nullptr, W_dec2, t, N1, h, N2, C1i, C1v, enc1);
    agg_k<0><<<cdiv(N2, 8), AT>>>(t, N1, rp2, src2, dis2, N2, b_dec2, h2, nullptr, nullptr, nullptr);  // out: N2 rows
    // ---- decoder l=1: gemm fuses unpool C0 (h2 has N2 rows, clamped) ----
    gemm_k<128, true><<<cdiv(N0, 128), 256, S128>>>(nullptr, W_dec1, t, N0, h2, N2, C0i, C0v, enc0);
    agg_k<0><<<cdiv(N1, 8), AT>>>(t, N0, rp1, src1, dis1, N1, b_dec1, h, nullptr, nullptr, nullptr);  // out: N1 rows
    // ---- decoder l=0 + fused normalize ----
    gemm_k<128, false><<<cdiv(N1, 128), 256, S128>>>(h, W_dec0, t, N1, nullptr, 0, nullptr, nullptr, nullptr);
    agg_k<2><<<cdiv(N0, 8), AT>>>(t, N1, rp0, src0, dis0, N0, b_dec0, (float*)d_out, nullptr, nullptr, nullptr);
}

// round 4
// speedup vs baseline: 1.7747x; 1.0733x over previous
#include <cuda_runtime.h>
#include <cuda_bf16.h>
#include <cuda_fp16.h>

#define N0 50000
#define N1 12500
#define N2 3125
#define E0 800000
#define E1 200000
#define E2 50000
#define ET (E0 + E1 + E2)
#define NT (N0 + N1 + N2)
#define D 128

// tile mapping for scan: 4096 nodes per tile
#define T0 13
#define T1 4
#define T2 1
#define NB (T0 + T1 + T2)   // 18

#define RP0 0
#define RP1 (N0 + 1)
#define RP2 (N0 + N1 + 2)

// ---------------- scratch (device globals) ----------------
__device__ __half g_t[N0 * D];     // GEMM output, fp16 (agg gathers this)
__device__ float g_enc0[N0 * D];
__device__ float g_enc1[N1 * D];
__device__ float g_h[N0 * D];
__device__ float g_h2[N0 * D];

__device__ int   g_deg[NT];
__device__ int   g_rp[NT + 3];
__device__ int   g_cur[NT];
__device__ float g_dis[NT];
__device__ int   g_src[ET];

// ---------------- f32x2 helpers ----------------
typedef unsigned long long u64;

__device__ __forceinline__ u64 pack2(float x) {
    u64 r;
    asm("mov.b64 %0, {%1, %1};" : "=l"(r) : "f"(x));
    return r;
}
__device__ __forceinline__ void fma2(u64& d, u64 a, u64 b) {
    asm("fma.rn.f32x2 %0, %1, %2, %0;" : "+l"(d) : "l"(a), "l"(b));
}
__device__ __forceinline__ float2 unpack2(u64 v) {
    float2 r;
    asm("mov.b64 {%0, %1}, %2;" : "=f"(r.x), "=f"(r.y) : "l"(v));
    return r;
}

// load 4 halfs (cols 4*lane .. 4*lane+3) of row r as float4
__device__ __forceinline__ float4 ld_h4(const __half* __restrict__ t, size_t r, int lane) {
    uint2 raw = ((const uint2*)(t + r * D))[lane];
    float2 a = __half22float2(*(__half2*)&raw.x);
    float2 b = __half22float2(*(__half2*)&raw.y);
    return make_float4(a.x, a.y, b.x, b.y);
}

// ---------------- utility kernels ----------------
__global__ void zero_init_k(int* deg, float4* h) {
    int i = blockIdx.x * blockDim.x + threadIdx.x;
    if (i < NT) deg[i] = 0;
    int nh = N1 * D / 4;
    for (int j = i; j < nh; j += gridDim.x * blockDim.x)
        h[j] = make_float4(0.f, 0.f, 0.f, 0.f);
}

__global__ void zero_f4_k(float4* p, int n4) {
    int i = blockIdx.x * blockDim.x + threadIdx.x;
    if (i < n4) p[i] = make_float4(0.f, 0.f, 0.f, 0.f);
}

// ---------------- CSR build: hist (all 3 graphs, int4 ILP) ----------------
__global__ void hist4_k(const int* __restrict__ e0, const int* __restrict__ e1,
                        const int* __restrict__ e2, int* __restrict__ deg) {
    int i = blockIdx.x * blockDim.x + threadIdx.x;
    int i4 = i * 4;
    int4 c;
    int base;
    if (i4 < E0)            { c = *(const int4*)(e0 + E0 + i4);            base = 0; }
    else if (i4 < E0 + E1)  { c = *(const int4*)(e1 + E1 + (i4 - E0));     base = N0; }
    else if (i4 < ET)       { c = *(const int4*)(e2 + E2 + (i4 - E0 - E1)); base = N0 + N1; }
    else return;
    atomicAdd(&deg[base + c.x], 1);
    atomicAdd(&deg[base + c.y], 1);
    atomicAdd(&deg[base + c.z], 1);
    atomicAdd(&deg[base + c.w], 1);
}

__device__ __forceinline__ void tile_map(int b, int& noff, int& ng, int& t, int& rpoff) {
    if (b < T0)           { noff = 0;       ng = N0; t = b;           rpoff = RP0; }
    else if (b < T0 + T1) { noff = N0;      ng = N1; t = b - T0;      rpoff = RP1; }
    else                  { noff = N0 + N1; ng = N2; t = b - T0 - T1; rpoff = RP2; }
}

// ---------------- fused scan ----------------
__global__ void scan_fused_k(const int* __restrict__ deg, int* __restrict__ rp,
                             int* __restrict__ cur, float* __restrict__ dis) {
    int noff, ng, t, rpoff;
    tile_map(blockIdx.x, noff, ng, t, rpoff);
    int tid = threadIdx.x;
    int lane = tid & 31, w = tid >> 5;
    __shared__ int ws[32];
    __shared__ int s_pre;

    {
        int lim = t * 4096;
        int s = 0;
        for (int i = tid * 4; i < lim; i += 4096) {
            int4 v = *(const int4*)(deg + noff + i);
            s += v.x + v.y + v.z + v.w;
        }
#pragma unroll
        for (int o = 16; o; o >>= 1) s += __shfl_xor_sync(0xffffffffu, s, o);
        if (lane == 0) ws[w] = s;
        __syncthreads();
        if (w == 0) {
            int v = ws[lane];
#pragma unroll
            for (int o = 16; o; o >>= 1) v += __shfl_xor_sync(0xffffffffu, v, o);
            if (lane == 0) s_pre = v;
        }
        __syncthreads();
    }

    int i = t * 4096 + tid * 4;
    int v[4];
    int s = 0;
#pragma unroll
    for (int q = 0; q < 4; q++) {
        int l = i + q;
        v[q] = (l < ng) ? deg[noff + l] : 0;
        s += v[q];
    }
    int incl = s;
#pragma unroll
    for (int o = 1; o < 32; o <<= 1) {
        int tv = __shfl_up_sync(0xffffffffu, incl, o);
        if (lane >= o) incl += tv;
    }
    __syncthreads();
    if (lane == 31) ws[w] = incl;
    __syncthreads();
    if (w == 0) {
        int x = ws[lane];
#pragma unroll
        for (int o = 1; o < 32; o <<= 1) {
            int tv = __shfl_up_sync(0xffffffffu, x, o);
            if (lane >= o) x += tv;
        }
        ws[lane] = x;
    }
    __syncthreads();
    int base = s_pre + (w > 0 ? ws[w - 1] : 0) + (incl - s);
    int run = base;
#pragma unroll
    for (int q = 0; q < 4; q++) {
        int l = i + q;
        if (l < ng) {
            rp[rpoff + l] = run;
            cur[noff + l] = run;
            dis[noff + l] = rsqrtf((float)(v[q] + 1));
            run += v[q];
        }
    }
    bool last = (t == ((ng + 4095) / 4096) - 1);
    if (last && tid == 1023) rp[rpoff + ng] = s_pre + ws[31];
}

// ---------------- CSR scatter (all 3 graphs, batched atomics for MLP) ----------------
__global__ void scatter4_k(const int* __restrict__ e0, const int* __restrict__ e1,
                           const int* __restrict__ e2, int* __restrict__ cur,
                           int* __restrict__ src) {
    int i = blockIdx.x * blockDim.x + threadIdx.x;
    int i4 = i * 4;
    int4 c, r;
    int nb, sb;
    if (i4 < E0) {
        c = *(const int4*)(e0 + E0 + i4); r = *(const int4*)(e0 + i4);
        nb = 0; sb = 0;
    } else if (i4 < E0 + E1) {
        int j = i4 - E0;
        c = *(const int4*)(e1 + E1 + j); r = *(const int4*)(e1 + j);
        nb = N0; sb = E0;
    } else if (i4 < ET) {
        int j = i4 - E0 - E1;
        c = *(const int4*)(e2 + E2 + j); r = *(const int4*)(e2 + j);
        nb = N0 + N1; sb = E0 + E1;
    } else return;
    int p0 = atomicAdd(&cur[nb + c.x], 1);
    int p1 = atomicAdd(&cur[nb + c.y], 1);
    int p2 = atomicAdd(&cur[nb + c.z], 1);
    int p3 = atomicAdd(&cur[nb + c.w], 1);
    src[sb + p0] = r.x;
    src[sb + p1] = r.y;
    src[sb + p2] = r.z;
    src[sb + p3] = r.w;
}

// ---------------- GEMM: C_half[rows x 128] = A[rows x 128] @ W[128 x 128] -----------
// fp32 accumulate (packed f32x2), single fp16 rounding on store.
// GATHER: A row r = val[r] * hsrc[clamp(idx[r])] + enc[r]  (fused unpool)
template<int BM, bool GATHER>
__global__ __launch_bounds__(256) void gemm_k(const float* __restrict__ A,
                                              const float* __restrict__ W,
                                              __half* __restrict__ C, int rows,
                                              const float* __restrict__ hsrc, int h_rows,
                                              const int* __restrict__ idx,
                                              const float* __restrict__ val,
                                              const float* __restrict__ enc) {
    constexpr int TM = BM / 16;
    constexpr int AST = BM + 4;
    extern __shared__ float sm[];
    float* Ws = sm;                    // [128][128]
    float* As = sm + 128 * 128;        // [128 k][AST]
    int tid = threadIdx.x;
    int row0 = blockIdx.x * BM;

#pragma unroll
    for (int j = 0; j < 16; j++) {
        int idxw = tid + j * 256;
        ((float4*)Ws)[idxw] = ((const float4*)W)[idxw];
    }
    {
        int w = tid >> 5, l = tid & 31;
        int rsub = l >> 2, c4l = l & 3;
#pragma unroll
        for (int j = 0; j < BM / 8; j++) {
            int m = j * 8 + w;
            int rblk = m % (BM / 8);
            int cblk = m / (BM / 8);
            int r = rblk * 8 + rsub;
            int c4 = cblk * 4 + c4l;
            float4 v = make_float4(0.f, 0.f, 0.f, 0.f);
            int gr = row0 + r;
            if (gr < rows) {
                if (GATHER) {
                    int c = min(idx[gr], h_rows - 1);
                    float vv = val[gr];
                    float4 u = *(const float4*)(hsrc + (size_t)c * D + c4 * 4);
                    float4 e = *(const float4*)(enc + (size_t)gr * D + c4 * 4);
                    v = make_float4(vv * u.x + e.x, vv * u.y + e.y,
                                    vv * u.z + e.z, vv * u.w + e.w);
                } else {
                    v = *(const float4*)(A + (size_t)gr * D + c4 * 4);
                }
            }
            int kb = c4 * 4;
            As[(kb + 0) * AST + r] = v.x;
            As[(kb + 1) * AST + r] = v.y;
            As[(kb + 2) * AST + r] = v.z;
            As[(kb + 3) * AST + r] = v.w;
        }
    }
    __syncthreads();

    int tr = tid >> 4, tc = tid & 15;
    u64 acc[TM][4] = {};
#pragma unroll 4
    for (int kk = 0; kk < 128; kk++) {
        const ulonglong2* wp = (const ulonglong2*)(Ws + kk * 128 + tc * 8);
        ulonglong2 q0 = wp[0];
        ulonglong2 q1 = wp[1];
        float a[TM];
        const float* ap = As + kk * AST + tr * TM;
        if (TM == 8) {
            float4 a0 = *(const float4*)ap;
            float4 a1 = *(const float4*)(ap + 4);
            a[0] = a0.x; a[1] = a0.y; a[2] = a0.z; a[3] = a0.w;
            a[4] = a1.x; a[5] = a1.y; a[6] = a1.z; a[7] = a1.w;
        } else {
            float2 a0 = *(const float2*)ap;
            a[0] = a0.x; a[1] = a0.y;
        }
#pragma unroll
        for (int i = 0; i < TM; i++) {
            u64 av = pack2(a[i]);
            fma2(acc[i][0], av, q0.x);
            fma2(acc[i][1], av, q0.y);
            fma2(acc[i][2], av, q1.x);
            fma2(acc[i][3], av, q1.y);
        }
    }
#pragma unroll
    for (int i = 0; i < TM; i++) {
        int gr = row0 + tr * TM + i;
        if (gr < rows) {
            __half2 q[4];
            q[0] = __float22half2_rn(unpack2(acc[i][0]));
            q[1] = __float22half2_rn(unpack2(acc[i][1]));
            q[2] = __float22half2_rn(unpack2(acc[i][2]));
            q[3] = __float22half2_rn(unpack2(acc[i][3]));
            *(uint4*)(C + (size_t)gr * D + tc * 8) = *(uint4*)q;
        }
    }
}

// ---------------- aggregation (warp/dst, unroll4, fp16 gathers, fp32 accumulate) ----
template<int MODE>   // 0 = plain, 1 = fused pool scatter, 2 = fused normalize
__global__ void agg_k(const __half* __restrict__ t, int h_rows,
                      const int* __restrict__ rp, const int* __restrict__ src,
                      const float* __restrict__ dis, int n,
                      const float* __restrict__ bias, float* __restrict__ out,
                      const int* __restrict__ pidx, const float* __restrict__ pval,
                      float* __restrict__ pout) {
    int warp = (blockIdx.x * blockDim.x + threadIdx.x) >> 5;
    int lane = threadIdx.x & 31;
    if (warp >= n) return;
    int dst = warp;
    float dd = dis[dst];
    int hc = h_rows - 1;
    float4 v = ld_h4(t, (size_t)min(dst, hc), lane);
    float w0 = dd * dd;
    float4 a1 = make_float4(w0 * v.x, w0 * v.y, w0 * v.z, w0 * v.w);
    float4 a2 = make_float4(0.f, 0.f, 0.f, 0.f);
    float4 a3 = make_float4(0.f, 0.f, 0.f, 0.f);
    float4 a4 = make_float4(0.f, 0.f, 0.f, 0.f);
    int e = rp[dst], end = rp[dst + 1];
    for (; e + 4 <= end; e += 4) {
        int s0 = src[e], s1 = src[e + 1], s2 = src[e + 2], s3 = src[e + 3];
        float q0 = dis[s0] * dd, q1 = dis[s1] * dd;
        float q2 = dis[s2] * dd, q3 = dis[s3] * dd;
        float4 u0 = ld_h4(t, (size_t)min(s0, hc), lane);
        float4 u1 = ld_h4(t, (size_t)min(s1, hc), lane);
        float4 u2 = ld_h4(t, (size_t)min(s2, hc), lane);
        float4 u3 = ld_h4(t, (size_t)min(s3, hc), lane);
        a1.x += q0 * u0.x; a1.y += q0 * u0.y; a1.z += q0 * u0.z; a1.w += q0 * u0.w;
        a2.x += q1 * u1.x; a2.y += q1 * u1.y; a2.z += q1 * u1.z; a2.w += q1 * u1.w;
        a3.x += q2 * u2.x; a3.y += q2 * u2.y; a3.z += q2 * u2.z; a3.w += q2 * u2.w;
        a4.x += q3 * u3.x; a4.y += q3 * u3.y; a4.z += q3 * u3.z; a4.w += q3 * u3.w;
    }
    for (; e < end; e++) {
        int s0 = src[e];
        float q0 = dis[s0] * dd;
        float4 u0 = ld_h4(t, (size_t)min(s0, hc), lane);
        a1.x += q0 * u0.x; a1.y += q0 * u0.y; a1.z += q0 * u0.z; a1.w += q0 * u0.w;
    }
    float4 b = ((const float4*)bias)[lane];
    float4 r;
    r.x = fmaxf(a1.x + a2.x + a3.x + a4.x + b.x, 0.f);
    r.y = fmaxf(a1.y + a2.y + a3.y + a4.y + b.y, 0.f);
    r.z = fmaxf(a1.z + a2.z + a3.z + a4.z + b.z, 0.f);
    r.w = fmaxf(a1.w + a2.w + a3.w + a4.w + b.w, 0.f);
    if (MODE == 2) {
        float s = r.x * r.x + r.y * r.y + r.z * r.z + r.w * r.w;
#pragma unroll
        for (int o = 16; o; o >>= 1) s += __shfl_xor_sync(0xffffffffu, s, o);
        float inv = 1.0f / fmaxf(sqrtf(s), 1e-12f);
        r.x *= inv; r.y *= inv; r.z *= inv; r.w *= inv;
    }
    ((float4*)(out + (size_t)dst * D))[lane] = r;
    if (MODE == 1) {
        int c = pidx[dst];
        float pv = pval[dst];
        float* o = pout + (size_t)c * D + lane * 4;
        atomicAdd(o + 0, pv * r.x);
        atomicAdd(o + 1, pv * r.y);
        atomicAdd(o + 2, pv * r.z);
        atomicAdd(o + 3, pv * r.w);
    }
}

// ---------------- host orchestration ----------------
static inline int cdiv(int a, int b) { return (a + b - 1) / b; }

extern "C" void kernel_launch(void* const* d_in, const int* in_sizes, int n_in,
                              void* d_out, int out_size) {
    const float* x   = (const float*)d_in[0];
    const int* e0    = (const int*)d_in[1];
    const int* e1    = (const int*)d_in[2];
    const int* e2    = (const int*)d_in[3];
    const int* C0i   = (const int*)d_in[4];
    const float* C0v = (const float*)d_in[5];
    const int* C1i   = (const int*)d_in[6];
    const float* C1v = (const float*)d_in[7];
    const float* W_enc0 = (const float*)d_in[8];
    const float* b_enc0 = (const float*)d_in[9];
    const float* W_enc1 = (const float*)d_in[10];
    const float* b_enc1 = (const float*)d_in[11];
    const float* W_enc2 = (const float*)d_in[12];
    const float* b_enc2 = (const float*)d_in[13];
    const float* W_bot  = (const float*)d_in[14];
    const float* b_bot  = (const float*)d_in[15];
    const float* W_dec0 = (const float*)d_in[16];
    const float* b_dec0 = (const float*)d_in[17];
    const float* W_dec1 = (const float*)d_in[18];
    const float* b_dec1 = (const float*)d_in[19];
    const float* W_dec2 = (const float*)d_in[20];
    const float* b_dec2 = (const float*)d_in[21];

    __half* t;
    float *enc0, *enc1, *h, *h2, *dis;
    int *deg, *rp, *cur, *src;
    cudaGetSymbolAddress((void**)&t, g_t);
    cudaGetSymbolAddress((void**)&enc0, g_enc0);
    cudaGetSymbolAddress((void**)&enc1, g_enc1);
    cudaGetSymbolAddress((void**)&h, g_h);
    cudaGetSymbolAddress((void**)&h2, g_h2);
    cudaGetSymbolAddress((void**)&deg, g_deg);
    cudaGetSymbolAddress((void**)&rp, g_rp);
    cudaGetSymbolAddress((void**)&cur, g_cur);
    cudaGetSymbolAddress((void**)&src, g_src);
    cudaGetSymbolAddress((void**)&dis, g_dis);

    const int S128 = (128 * 128 + 128 * (128 + 4)) * (int)sizeof(float);
    const int S32  = (128 * 128 + 128 * (32 + 4)) * (int)sizeof(float);
    cudaFuncSetAttribute((const void*)gemm_k<128, false>, cudaFuncAttributeMaxDynamicSharedMemorySize, S128);
    cudaFuncSetAttribute((const void*)gemm_k<128, true>,  cudaFuncAttributeMaxDynamicSharedMemorySize, S128);
    cudaFuncSetAttribute((const void*)gemm_k<32, false>,  cudaFuncAttributeMaxDynamicSharedMemorySize, S32);

    const int* rp0 = rp + RP0; const int* src0 = src;           const float* dis0 = dis;
    const int* rp1 = rp + RP1; const int* src1 = src + E0;      const float* dis1 = dis + N0;
    const int* rp2 = rp + RP2; const int* src2 = src + E0 + E1; const float* dis2 = dis + N0 + N1;

    const int AT = 256;

    // ---- CSR build (all 3 graphs) + zero h(N1 rows) ----
    zero_init_k<<<cdiv(NT, 1024), 1024>>>(deg, (float4*)h);
    hist4_k<<<cdiv(ET / 4, 256), 256>>>(e0, e1, e2, deg);
    scan_fused_k<<<NB, 1024>>>(deg, rp, cur, dis);
    scatter4_k<<<cdiv(ET / 4, 256), 256>>>(e0, e1, e2, cur, src);

    // ---- encoder level 0 (agg fuses pool0 -> h) ----
    gemm_k<128, false><<<cdiv(N0, 128), 256, S128>>>(x, W_enc0, t, N0, nullptr, 0, nullptr, nullptr, nullptr);
    agg_k<1><<<cdiv(N0, 8), AT>>>(t, N0, rp0, src0, dis0, N0, b_enc0, enc0, C0i, C0v, h);
    // ---- encoder level 1 (agg fuses pool1 -> h, re-zeroed after gemm read) ----
    gemm_k<128, false><<<cdiv(N1, 128), 256, S128>>>(h, W_enc1, t, N1, nullptr, 0, nullptr, nullptr, nullptr);
    zero_f4_k<<<cdiv(N2 * D / 4, 256), 256>>>((float4*)h, N2 * D / 4);
    agg_k<1><<<cdiv(N1, 8), AT>>>(t, N1, rp1, src1, dis1, N1, b_enc1, enc1, C1i, C1v, h);
    // ---- encoder level 2 ----
    gemm_k<32, false><<<cdiv(N2, 32), 256, S32>>>(h, W_enc2, t, N2, nullptr, 0, nullptr, nullptr, nullptr);
    agg_k<0><<<cdiv(N2, 8), AT>>>(t, N2, rp2, src2, dis2, N2, b_enc2, h2, nullptr, nullptr, nullptr);
    // ---- bottleneck ----
    gemm_k<32, false><<<cdiv(N2, 32), 256, S32>>>(h2, W_bot, t, N2, nullptr, 0, nullptr, nullptr, nullptr);
    agg_k<0><<<cdiv(N2, 8), AT>>>(t, N2, rp2, src2, dis2, N2, b_bot, h, nullptr, nullptr, nullptr);
    // ---- decoder l=2: gemm fuses unpool C1 (h has N2 rows) ----
    gemm_k<128, true><<<cdiv(N1, 128), 256, S128>>>(nullptr, W_dec2, t, N1, h, N2, C1i, C1v, enc1);
    agg_k<0><<<cdiv(N2, 8), AT>>>(t, N1, rp2, src2, dis2, N2, b_dec2, h2, nullptr, nullptr, nullptr);
    // ---- decoder l=1: gemm fuses unpool C0 (h2 has N2 rows, clamped) ----
    gemm_k<128, true><<<cdiv(N0, 128), 256, S128>>>(nullptr, W_dec1, t, N0, h2, N2, C0i, C0v, enc0);
    agg_k<0><<<cdiv(N1, 8), AT>>>(t, N0, rp1, src1, dis1, N1, b_dec1, h, nullptr, nullptr, nullptr);
    // ---- decoder l=0 + fused normalize ----
    gemm_k<128, false><<<cdiv(N1, 128), 256, S128>>>(h, W_dec0, t, N1, nullptr, 0, nullptr, nullptr, nullptr);
    agg_k<2><<<cdiv(N0, 8), AT>>>(t, N1, rp0, src0, dis0, N0, b_dec0, (float*)d_out, nullptr, nullptr, nullptr);
}

// round 5
// speedup vs baseline: 2.2708x; 1.2795x over previous
#include <cuda_runtime.h>
#include <cuda_bf16.h>
#include <cuda_fp16.h>

#define N0 50000
#define N1 12500
#define N2 3125
#define E0 800000
#define E1 200000
#define E2 50000
#define ET (E0 + E1 + E2)
#define NT (N0 + N1 + N2)
#define D 128

#define T0 13
#define T1 4
#define T2 1
#define NB (T0 + T1 + T2)

#define RP0 0
#define RP1 (N0 + 1)
#define RP2 (N0 + N1 + 2)

// ---------------- scratch (device globals) ----------------
__device__ __half g_t[N0 * D];
__device__ float g_enc0[N0 * D];
__device__ float g_enc1[N1 * D];
__device__ float g_h[N0 * D];
__device__ float g_h2[N0 * D];

__device__ int   g_deg[NT];
__device__ int   g_rp[NT + 3];
__device__ int   g_cur[NT];
__device__ float g_dis[NT];
__device__ int   g_src[ET];

// ---------------- helpers ----------------
__device__ __forceinline__ float4 ld_h4(const __half* __restrict__ t, size_t r, int lane) {
    uint2 raw = ((const uint2*)(t + r * D))[lane];
    float2 a = __half22float2(*(__half2*)&raw.x);
    float2 b = __half22float2(*(__half2*)&raw.y);
    return make_float4(a.x, a.y, b.x, b.y);
}

__device__ __forceinline__ unsigned tf32_of(float x) {
    unsigned r;
    asm("cvt.rna.tf32.f32 %0, %1;" : "=r"(r) : "f"(x));
    return r;
}

__device__ __forceinline__ void mma_tf32(float* d, const unsigned* a, unsigned b0, unsigned b1) {
    asm volatile(
        "mma.sync.aligned.m16n8k8.row.col.f32.tf32.tf32.f32 "
        "{%0,%1,%2,%3}, {%4,%5,%6,%7}, {%8,%9}, {%0,%1,%2,%3};"
        : "+f"(d[0]), "+f"(d[1]), "+f"(d[2]), "+f"(d[3])
        : "r"(a[0]), "r"(a[1]), "r"(a[2]), "r"(a[3]), "r"(b0), "r"(b1));
}

// ---------------- utility kernels ----------------
__global__ void zero_init_k(int* deg, float4* h) {
    int i = blockIdx.x * blockDim.x + threadIdx.x;
    if (i < NT) deg[i] = 0;
    int nh = N1 * D / 4;
    for (int j = i; j < nh; j += gridDim.x * blockDim.x)
        h[j] = make_float4(0.f, 0.f, 0.f, 0.f);
}

__global__ void zero_f4_k(float4* p, int n4) {
    int i = blockIdx.x * blockDim.x + threadIdx.x;
    if (i < n4) p[i] = make_float4(0.f, 0.f, 0.f, 0.f);
}

// ---------------- CSR build: histogram, ILP8 ----------------
__global__ void hist8_k(const int* __restrict__ e0, const int* __restrict__ e1,
                        const int* __restrict__ e2, int* __restrict__ deg) {
    int i = blockIdx.x * blockDim.x + threadIdx.x;
    int i8 = i * 8;
    const int* p;
    int base;
    if (i8 < E0)           { p = e0 + E0 + i8;            base = 0; }
    else if (i8 < E0 + E1) { p = e1 + E1 + (i8 - E0);     base = N0; }
    else if (i8 < ET)      { p = e2 + E2 + (i8 - E0 - E1); base = N0 + N1; }
    else return;
    int4 c0 = *(const int4*)p;
    int4 c1 = *(const int4*)(p + 4);
    atomicAdd(&deg[base + c0.x], 1); atomicAdd(&deg[base + c0.y], 1);
    atomicAdd(&deg[base + c0.z], 1); atomicAdd(&deg[base + c0.w], 1);
    atomicAdd(&deg[base + c1.x], 1); atomicAdd(&deg[base + c1.y], 1);
    atomicAdd(&deg[base + c1.z], 1); atomicAdd(&deg[base + c1.w], 1);
}

__device__ __forceinline__ void tile_map(int b, int& noff, int& ng, int& t, int& rpoff) {
    if (b < T0)           { noff = 0;       ng = N0; t = b;           rpoff = RP0; }
    else if (b < T0 + T1) { noff = N0;      ng = N1; t = b - T0;      rpoff = RP1; }
    else                  { noff = N0 + N1; ng = N2; t = b - T0 - T1; rpoff = RP2; }
}

// ---------------- fused scan ----------------
__global__ void scan_fused_k(const int* __restrict__ deg, int* __restrict__ rp,
                             int* __restrict__ cur, float* __restrict__ dis) {
    int noff, ng, t, rpoff;
    tile_map(blockIdx.x, noff, ng, t, rpoff);
    int tid = threadIdx.x;
    int lane = tid & 31, w = tid >> 5;
    __shared__ int ws[32];
    __shared__ int s_pre;

    {
        int lim = t * 4096;
        int s = 0;
        for (int i = tid * 4; i < lim; i += 4096) {
            int4 v = *(const int4*)(deg + noff + i);
            s += v.x + v.y + v.z + v.w;
        }
#pragma unroll
        for (int o = 16; o; o >>= 1) s += __shfl_xor_sync(0xffffffffu, s, o);
        if (lane == 0) ws[w] = s;
        __syncthreads();
        if (w == 0) {
            int v = ws[lane];
#pragma unroll
            for (int o = 16; o; o >>= 1) v += __shfl_xor_sync(0xffffffffu, v, o);
            if (lane == 0) s_pre = v;
        }
        __syncthreads();
    }

    int i = t * 4096 + tid * 4;
    int v[4];
    int s = 0;
#pragma unroll
    for (int q = 0; q < 4; q++) {
        int l = i + q;
        v[q] = (l < ng) ? deg[noff + l] : 0;
        s += v[q];
    }
    int incl = s;
#pragma unroll
    for (int o = 1; o < 32; o <<= 1) {
        int tv = __shfl_up_sync(0xffffffffu, incl, o);
        if (lane >= o) incl += tv;
    }
    __syncthreads();
    if (lane == 31) ws[w] = incl;
    __syncthreads();
    if (w == 0) {
        int x = ws[lane];
#pragma unroll
        for (int o = 1; o < 32; o <<= 1) {
            int tv = __shfl_up_sync(0xffffffffu, x, o);
            if (lane >= o) x += tv;
        }
        ws[lane] = x;
    }
    __syncthreads();
    int base = s_pre + (w > 0 ? ws[w - 1] : 0) + (incl - s);
    int run = base;
#pragma unroll
    for (int q = 0; q < 4; q++) {
        int l = i + q;
        if (l < ng) {
            rp[rpoff + l] = run;
            cur[noff + l] = run;
            dis[noff + l] = rsqrtf((float)(v[q] + 1));
            run += v[q];
        }
    }
    bool last = (t == ((ng + 4095) / 4096) - 1);
    if (last && tid == 1023) rp[rpoff + ng] = s_pre + ws[31];
}

// ---------------- CSR scatter, ILP8 ----------------
__global__ void scatter8_k(const int* __restrict__ e0, const int* __restrict__ e1,
                           const int* __restrict__ e2, int* __restrict__ cur,
                           int* __restrict__ src) {
    int i = blockIdx.x * blockDim.x + threadIdx.x;
    int i8 = i * 8;
    const int* pe;
    int nb, sb, E;
    if (i8 < E0)           { pe = e0; nb = 0;       sb = 0;       E = E0; i8 -= 0; }
    else if (i8 < E0 + E1) { pe = e1; nb = N0;      sb = E0;      E = E1; i8 -= E0; }
    else if (i8 < ET)      { pe = e2; nb = N0 + N1; sb = E0 + E1; E = E2; i8 -= E0 + E1; }
    else return;
    int4 c0 = *(const int4*)(pe + E + i8);
    int4 c1 = *(const int4*)(pe + E + i8 + 4);
    int4 r0 = *(const int4*)(pe + i8);
    int4 r1 = *(const int4*)(pe + i8 + 4);
    int p0 = atomicAdd(&cur[nb + c0.x], 1);
    int p1 = atomicAdd(&cur[nb + c0.y], 1);
    int p2 = atomicAdd(&cur[nb + c0.z], 1);
    int p3 = atomicAdd(&cur[nb + c0.w], 1);
    int p4 = atomicAdd(&cur[nb + c1.x], 1);
    int p5 = atomicAdd(&cur[nb + c1.y], 1);
    int p6 = atomicAdd(&cur[nb + c1.z], 1);
    int p7 = atomicAdd(&cur[nb + c1.w], 1);
    src[sb + p0] = r0.x; src[sb + p1] = r0.y;
    src[sb + p2] = r0.z; src[sb + p3] = r0.w;
    src[sb + p4] = r1.x; src[sb + p5] = r1.y;
    src[sb + p6] = r1.z; src[sb + p7] = r1.w;
}

// ---------------- tensor-core GEMM (tf32 mma.sync), persistent, double-buffered ----
// C_half[rows x 128] = A[rows x 128] @ W[128 x 128]; fp32 accumulate, fp16 store.
// GATHER: A row r = val[r] * hsrc[clamp(idx[r])] + enc[r]  (fused unpool)
#define WS_STRIDE 136
#define AS_STRIDE 132
#define SMEM_TC ((128 * WS_STRIDE + 2 * 128 * AS_STRIDE) * 4)

template<bool GATHER>
__global__ __launch_bounds__(512, 1) void gemm_tc(
    const float* __restrict__ A, const float* __restrict__ W,
    __half* __restrict__ C, int rows,
    const float* __restrict__ hsrc, int h_rows,
    const int* __restrict__ idx, const float* __restrict__ val,
    const float* __restrict__ enc)
{
    extern __shared__ float sm[];
    float* Ws = sm;                          // [128][136] tf32 bits
    float* As[2] = { sm + 128 * WS_STRIDE,   // [128][132] tf32 bits
                     sm + 128 * WS_STRIDE + 128 * AS_STRIDE };
    int tid = threadIdx.x;
    int lane = tid & 31;
    int w = tid >> 5;            // 0..15
    int wm = w & 3, wn = w >> 2; // 4x4 warp grid, warp tile 32x32
    int gid = lane >> 2, tig = lane & 3;

    int tiles = (rows + 127) >> 7;

    // ---- load W once (tf32 convert) ----
#pragma unroll
    for (int j = 0; j < 8; j++) {
        int linear = tid + j * 512;
        int k = linear >> 5, c4 = linear & 31;
        float4 v = *(const float4*)(W + k * 128 + c4 * 4);
        uint4 q;
        q.x = tf32_of(v.x); q.y = tf32_of(v.y);
        q.z = tf32_of(v.z); q.w = tf32_of(v.w);
        *(uint4*)(Ws + k * WS_STRIDE + c4 * 4) = q;
    }

    // staging: chunk c covers row (w + c*16), cols lane*4 .. lane*4+3
    float4 st[8];
    auto load_tile = [&](int tile) {
#pragma unroll
        for (int c = 0; c < 8; c++) {
            int r = w + c * 16;
            int gr = tile * 128 + r;
            float4 v = make_float4(0.f, 0.f, 0.f, 0.f);
            if (gr < rows) {
                if (GATHER) {
                    int ci = min(idx[gr], h_rows - 1);
                    float vv = val[gr];
                    float4 u = *(const float4*)(hsrc + (size_t)ci * D + lane * 4);
                    float4 e = *(const float4*)(enc + (size_t)gr * D + lane * 4);
                    v = make_float4(vv * u.x + e.x, vv * u.y + e.y,
                                    vv * u.z + e.z, vv * u.w + e.w);
                } else {
                    v = *(const float4*)(A + (size_t)gr * D + lane * 4);
                }
            }
            st[c] = v;
        }
    };
    auto store_tile = [&](float* dst) {
#pragma unroll
        for (int c = 0; c < 8; c++) {
            int r = w + c * 16;
            uint4 q;
            q.x = tf32_of(st[c].x); q.y = tf32_of(st[c].y);
            q.z = tf32_of(st[c].z); q.w = tf32_of(st[c].w);
            *(uint4*)(dst + r * AS_STRIDE + lane * 4) = q;
        }
    };

    int t = blockIdx.x;
    if (t < tiles) load_tile(t);
    store_tile(As[0]);
    __syncthreads();

    int buf = 0;
    for (; t < tiles; t += gridDim.x) {
        int tn = t + gridDim.x;
        bool hasnext = tn < tiles;
        if (hasnext) load_tile(tn);    // LDG in flight during compute

        // ---- compute 128x128 tile ----
        float acc[2][4][4];
#pragma unroll
        for (int mt = 0; mt < 2; mt++)
#pragma unroll
            for (int nt = 0; nt < 4; nt++)
#pragma unroll
                for (int q = 0; q < 4; q++) acc[mt][nt][q] = 0.f;

        const float* Ac = As[buf];
#pragma unroll 4
        for (int ks = 0; ks < 16; ks++) {
            int k0 = ks * 8;
            unsigned a[2][4];
#pragma unroll
            for (int mt = 0; mt < 2; mt++) {
                const float* base = Ac + (wm * 32 + mt * 16 + gid) * AS_STRIDE + k0 + tig;
                a[mt][0] = __float_as_uint(base[0]);
                a[mt][1] = __float_as_uint(base[8 * AS_STRIDE]);
                a[mt][2] = __float_as_uint(base[4]);
                a[mt][3] = __float_as_uint(base[8 * AS_STRIDE + 4]);
            }
#pragma unroll
            for (int nt = 0; nt < 4; nt++) {
                int n = wn * 32 + nt * 8 + gid;
                unsigned b0 = __float_as_uint(Ws[(k0 + tig) * WS_STRIDE + n]);
                unsigned b1 = __float_as_uint(Ws[(k0 + tig + 4) * WS_STRIDE + n]);
                mma_tf32(acc[0][nt], a[0], b0, b1);
                mma_tf32(acc[1][nt], a[1], b0, b1);
            }
        }

        // ---- epilogue: fp16 store ----
#pragma unroll
        for (int mt = 0; mt < 2; mt++) {
            int r1 = t * 128 + wm * 32 + mt * 16 + gid;
            int r2 = r1 + 8;
#pragma unroll
            for (int nt = 0; nt < 4; nt++) {
                int col = wn * 32 + nt * 8 + 2 * tig;
                if (r1 < rows)
                    *(__half2*)(C + (size_t)r1 * D + col) =
                        __floats2half2_rn(acc[mt][nt][0], acc[mt][nt][1]);
                if (r2 < rows)
                    *(__half2*)(C + (size_t)r2 * D + col) =
                        __floats2half2_rn(acc[mt][nt][2], acc[mt][nt][3]);
            }
        }

        if (hasnext) {
            store_tile(As[buf ^ 1]);
            __syncthreads();
            buf ^= 1;
        }
    }
}

// ---------------- aggregation (warp/dst, unroll4, fp16 gathers, fp32 accumulate) ----
template<int MODE>   // 0 = plain, 1 = fused pool scatter, 2 = fused normalize
__global__ void agg_k(const __half* __restrict__ t, int h_rows,
                      const int* __restrict__ rp, const int* __restrict__ src,
                      const float* __restrict__ dis, int n,
                      const float* __restrict__ bias, float* __restrict__ out,
                      const int* __restrict__ pidx, const float* __restrict__ pval,
                      float* __restrict__ pout) {
    int warp = (blockIdx.x * blockDim.x + threadIdx.x) >> 5;
    int lane = threadIdx.x & 31;
    if (warp >= n) return;
    int dst = warp;
    float dd = dis[dst];
    int hc = h_rows - 1;
    float4 v = ld_h4(t, (size_t)min(dst, hc), lane);
    float w0 = dd * dd;
    float4 a1 = make_float4(w0 * v.x, w0 * v.y, w0 * v.z, w0 * v.w);
    float4 a2 = make_float4(0.f, 0.f, 0.f, 0.f);
    float4 a3 = make_float4(0.f, 0.f, 0.f, 0.f);
    float4 a4 = make_float4(0.f, 0.f, 0.f, 0.f);
    int e = rp[dst], end = rp[dst + 1];
    for (; e + 4 <= end; e += 4) {
        int s0 = src[e], s1 = src[e + 1], s2 = src[e + 2], s3 = src[e + 3];
        float q0 = dis[s0] * dd, q1 = dis[s1] * dd;
        float q2 = dis[s2] * dd, q3 = dis[s3] * dd;
        float4 u0 = ld_h4(t, (size_t)min(s0, hc), lane);
        float4 u1 = ld_h4(t, (size_t)min(s1, hc), lane);
        float4 u2 = ld_h4(t, (size_t)min(s2, hc), lane);
        float4 u3 = ld_h4(t, (size_t)min(s3, hc), lane);
        a1.x += q0 * u0.x; a1.y += q0 * u0.y; a1.z += q0 * u0.z; a1.w += q0 * u0.w;
        a2.x += q1 * u1.x; a2.y += q1 * u1.y; a2.z += q1 * u1.z; a2.w += q1 * u1.w;
        a3.x += q2 * u2.x; a3.y += q2 * u2.y; a3.z += q2 * u2.z; a3.w += q2 * u2.w;
        a4.x += q3 * u3.x; a4.y += q3 * u3.y; a4.z += q3 * u3.z; a4.w += q3 * u3.w;
    }
    for (; e < end; e++) {
        int s0 = src[e];
        float q0 = dis[s0] * dd;
        float4 u0 = ld_h4(t, (size_t)min(s0, hc), lane);
        a1.x += q0 * u0.x; a1.y += q0 * u0.y; a1.z += q0 * u0.z; a1.w += q0 * u0.w;
    }
    float4 b = ((const float4*)bias)[lane];
    float4 r;
    r.x = fmaxf(a1.x + a2.x + a3.x + a4.x + b.x, 0.f);
    r.y = fmaxf(a1.y + a2.y + a3.y + a4.y + b.y, 0.f);
    r.z = fmaxf(a1.z + a2.z + a3.z + a4.z + b.z, 0.f);
    r.w = fmaxf(a1.w + a2.w + a3.w + a4.w + b.w, 0.f);
    if (MODE == 2) {
        float s = r.x * r.x + r.y * r.y + r.z * r.z + r.w * r.w;
#pragma unroll
        for (int o = 16; o; o >>= 1) s += __shfl_xor_sync(0xffffffffu, s, o);
        float inv = 1.0f / fmaxf(sqrtf(s), 1e-12f);
        r.x *= inv; r.y *= inv; r.z *= inv; r.w *= inv;
    }
    ((float4*)(out + (size_t)dst * D))[lane] = r;
    if (MODE == 1) {
        int c = pidx[dst];
        float pv = pval[dst];
        float* o = pout + (size_t)c * D + lane * 4;
        atomicAdd(o + 0, pv * r.x);
        atomicAdd(o + 1, pv * r.y);
        atomicAdd(o + 2, pv * r.z);
        atomicAdd(o + 3, pv * r.w);
    }
}

// ---------------- host orchestration ----------------
static inline int cdiv(int a, int b) { return (a + b - 1) / b; }

extern "C" void kernel_launch(void* const* d_in, const int* in_sizes, int n_in,
                              void* d_out, int out_size) {
    const float* x   = (const float*)d_in[0];
    const int* e0    = (const int*)d_in[1];
    const int* e1    = (const int*)d_in[2];
    const int* e2    = (const int*)d_in[3];
    const int* C0i   = (const int*)d_in[4];
    const float* C0v = (const float*)d_in[5];
    const int* C1i   = (const int*)d_in[6];
    const float* C1v = (const float*)d_in[7];
    const float* W_enc0 = (const float*)d_in[8];
    const float* b_enc0 = (const float*)d_in[9];
    const float* W_enc1 = (const float*)d_in[10];
    const float* b_enc1 = (const float*)d_in[11];
    const float* W_enc2 = (const float*)d_in[12];
    const float* b_enc2 = (const float*)d_in[13];
    const float* W_bot  = (const float*)d_in[14];
    const float* b_bot  = (const float*)d_in[15];
    const float* W_dec0 = (const float*)d_in[16];
    const float* b_dec0 = (const float*)d_in[17];
    const float* W_dec1 = (const float*)d_in[18];
    const float* b_dec1 = (const float*)d_in[19];
    const float* W_dec2 = (const float*)d_in[20];
    const float* b_dec2 = (const float*)d_in[21];

    __half* t;
    float *enc0, *enc1, *h, *h2, *dis;
    int *deg, *rp, *cur, *src;
    cudaGetSymbolAddress((void**)&t, g_t);
    cudaGetSymbolAddress((void**)&enc0, g_enc0);
    cudaGetSymbolAddress((void**)&enc1, g_enc1);
    cudaGetSymbolAddress((void**)&h, g_h);
    cudaGetSymbolAddress((void**)&h2, g_h2);
    cudaGetSymbolAddress((void**)&deg, g_deg);
    cudaGetSymbolAddress((void**)&rp, g_rp);
    cudaGetSymbolAddress((void**)&cur, g_cur);
    cudaGetSymbolAddress((void**)&src, g_src);
    cudaGetSymbolAddress((void**)&dis, g_dis);

    cudaFuncSetAttribute((const void*)gemm_tc<false>, cudaFuncAttributeMaxDynamicSharedMemorySize, SMEM_TC);
    cudaFuncSetAttribute((const void*)gemm_tc<true>,  cudaFuncAttributeMaxDynamicSharedMemorySize, SMEM_TC);

    const int* rp0 = rp + RP0; const int* src0 = src;           const float* dis0 = dis;
    const int* rp1 = rp + RP1; const int* src1 = src + E0;      const float* dis1 = dis + N0;
    const int* rp2 = rp + RP2; const int* src2 = src + E0 + E1; const float* dis2 = dis + N0 + N1;

    const int AT = 256;

    auto gemm = [&](const float* A, const float* W, int rows) {
        int grid = min(cdiv(rows, 128), 148);
        gemm_tc<false><<<grid, 512, SMEM_TC>>>(A, W, t, rows, nullptr, 0, nullptr, nullptr, nullptr);
    };
    auto gemm_g = [&](const float* W, int rows, const float* hsrc, int h_rows,
                      const int* idx, const float* val, const float* enc) {
        int grid = min(cdiv(rows, 128), 148);
        gemm_tc<true><<<grid, 512, SMEM_TC>>>(nullptr, W, t, rows, hsrc, h_rows, idx, val, enc);
    };

    // ---- CSR build (all 3 graphs) + zero h(N1 rows) ----
    zero_init_k<<<cdiv(NT, 1024), 1024>>>(deg, (float4*)h);
    hist8_k<<<cdiv(ET / 8, 256), 256>>>(e0, e1, e2, deg);
    scan_fused_k<<<NB, 1024>>>(deg, rp, cur, dis);
    scatter8_k<<<cdiv(ET / 8, 256), 256>>>(e0, e1, e2, cur, src);

    // ---- encoder level 0 (agg fuses pool0 -> h) ----
    gemm(x, W_enc0, N0);
    agg_k<1><<<cdiv(N0, 8), AT>>>(t, N0, rp0, src0, dis0, N0, b_enc0, enc0, C0i, C0v, h);
    // ---- encoder level 1 (agg fuses pool1 -> h, re-zeroed after gemm read) ----
    gemm(h, W_enc1, N1);
    zero_f4_k<<<cdiv(N2 * D / 4, 256), 256>>>((float4*)h, N2 * D / 4);
    agg_k<1><<<cdiv(N1, 8), AT>>>(t, N1, rp1, src1, dis1, N1, b_enc1, enc1, C1i, C1v, h);
    // ---- encoder level 2 ----
    gemm(h, W_enc2, N2);
    agg_k<0><<<cdiv(N2, 8), AT>>>(t, N2, rp2, src2, dis2, N2, b_enc2, h2, nullptr, nullptr, nullptr);
    // ---- bottleneck ----
    gemm(h2, W_bot, N2);
    agg_k<0><<<cdiv(N2, 8), AT>>>(t, N2, rp2, src2, dis2, N2, b_bot, h, nullptr, nullptr, nullptr);
    // ---- decoder l=2: gemm fuses unpool C1 (h has N2 rows) ----
    gemm_g(W_dec2, N1, h, N2, C1i, C1v, enc1);
    agg_k<0><<<cdiv(N2, 8), AT>>>(t, N1, rp2, src2, dis2, N2, b_dec2, h2, nullptr, nullptr, nullptr);
    // ---- decoder l=1: gemm fuses unpool C0 (h2 has N2 rows, clamped) ----
    gemm_g(W_dec1, N0, h2, N2, C0i, C0v, enc0);
    agg_k<0><<<cdiv(N1, 8), AT>>>(t, N0, rp1, src1, dis1, N1, b_dec1, h, nullptr, nullptr, nullptr);
    // ---- decoder l=0 + fused normalize ----
    gemm(h, W_dec0, N1);
    agg_k<2><<<cdiv(N0, 8), AT>>>(t, N1, rp0, src0, dis0, N0, b_dec0, (float*)d_out, nullptr, nullptr, nullptr);
}

// round 6
// speedup vs baseline: 2.3507x; 1.0352x over previous
#include <cuda_runtime.h>
#include <cuda_bf16.h>
#include <cuda_fp16.h>

#define N0 50000
#define N1 12500
#define N2 3125
#define E0 800000
#define E1 200000
#define E2 50000
#define ET (E0 + E1 + E2)
#define NT (N0 + N1 + N2)
#define D 128

#define T0 13
#define T1 4
#define T2 1
#define NB (T0 + T1 + T2)

#define RP0 0
#define RP1 (N0 + 1)
#define RP2 (N0 + N1 + 2)

// ---------------- scratch (device globals) ----------------
__device__ __half g_t[N0 * D];
__device__ float g_enc0[N0 * D];
__device__ float g_enc1[N1 * D];
__device__ float g_h[N0 * D];
__device__ float g_h2[N0 * D];

__device__ int   g_deg[NT];
__device__ int   g_rp[NT + 3];
__device__ int   g_cur[NT];
__device__ float g_dis[NT];
__device__ int2  g_es[ET];        // per-edge {src, bits(dis[src])}

// ---------------- helpers ----------------
__device__ __forceinline__ float4 ld_h4(const __half* __restrict__ t, size_t r, int lane) {
    uint2 raw = __ldg((const uint2*)(t + r * D) + lane);
    float2 a = __half22float2(*(__half2*)&raw.x);
    float2 b = __half22float2(*(__half2*)&raw.y);
    return make_float4(a.x, a.y, b.x, b.y);
}

__device__ __forceinline__ unsigned tf32_of(float x) {
    unsigned r;
    asm("cvt.rna.tf32.f32 %0, %1;" : "=r"(r) : "f"(x));
    return r;
}

__device__ __forceinline__ void mma_tf32(float* d, const unsigned* a, unsigned b0, unsigned b1) {
    asm volatile(
        "mma.sync.aligned.m16n8k8.row.col.f32.tf32.tf32.f32 "
        "{%0,%1,%2,%3}, {%4,%5,%6,%7}, {%8,%9}, {%0,%1,%2,%3};"
        : "+f"(d[0]), "+f"(d[1]), "+f"(d[2]), "+f"(d[3])
        : "r"(a[0]), "r"(a[1]), "r"(a[2]), "r"(a[3]), "r"(b0), "r"(b1));
}

// ---------------- utility kernels ----------------
// zero deg[NT], h[0 .. N1*D), h2[0 .. N2*D)
__global__ void zero_init_k(int* deg, float4* h, float4* h2) {
    int i = blockIdx.x * blockDim.x + threadIdx.x;
    if (i < NT) deg[i] = 0;
    int nh = N1 * D / 4;
    for (int j = i; j < nh; j += gridDim.x * blockDim.x)
        h[j] = make_float4(0.f, 0.f, 0.f, 0.f);
    int nh2 = N2 * D / 4;
    for (int j = i; j < nh2; j += gridDim.x * blockDim.x)
        h2[j] = make_float4(0.f, 0.f, 0.f, 0.f);
}

// ---------------- CSR build: histogram, ILP8 ----------------
__global__ void hist8_k(const int* __restrict__ e0, const int* __restrict__ e1,
                        const int* __restrict__ e2, int* __restrict__ deg) {
    int i = blockIdx.x * blockDim.x + threadIdx.x;
    int i8 = i * 8;
    const int* p;
    int base;
    if (i8 < E0)           { p = e0 + E0 + i8;             base = 0; }
    else if (i8 < E0 + E1) { p = e1 + E1 + (i8 - E0);      base = N0; }
    else if (i8 < ET)      { p = e2 + E2 + (i8 - E0 - E1); base = N0 + N1; }
    else return;
    int4 c0 = *(const int4*)p;
    int4 c1 = *(const int4*)(p + 4);
    atomicAdd(&deg[base + c0.x], 1); atomicAdd(&deg[base + c0.y], 1);
    atomicAdd(&deg[base + c0.z], 1); atomicAdd(&deg[base + c0.w], 1);
    atomicAdd(&deg[base + c1.x], 1); atomicAdd(&deg[base + c1.y], 1);
    atomicAdd(&deg[base + c1.z], 1); atomicAdd(&deg[base + c1.w], 1);
}

__device__ __forceinline__ void tile_map(int b, int& noff, int& ng, int& t, int& rpoff) {
    if (b < T0)           { noff = 0;       ng = N0; t = b;           rpoff = RP0; }
    else if (b < T0 + T1) { noff = N0;      ng = N1; t = b - T0;      rpoff = RP1; }
    else                  { noff = N0 + N1; ng = N2; t = b - T0 - T1; rpoff = RP2; }
}

// ---------------- fused scan ----------------
__global__ void scan_fused_k(const int* __restrict__ deg, int* __restrict__ rp,
                             int* __restrict__ cur, float* __restrict__ dis) {
    int noff, ng, t, rpoff;
    tile_map(blockIdx.x, noff, ng, t, rpoff);
    int tid = threadIdx.x;
    int lane = tid & 31, w = tid >> 5;
    __shared__ int ws[32];
    __shared__ int s_pre;

    {
        int lim = t * 4096;
        int s = 0;
        for (int i = tid * 4; i < lim; i += 4096) {
            int4 v = *(const int4*)(deg + noff + i);
            s += v.x + v.y + v.z + v.w;
        }
#pragma unroll
        for (int o = 16; o; o >>= 1) s += __shfl_xor_sync(0xffffffffu, s, o);
        if (lane == 0) ws[w] = s;
        __syncthreads();
        if (w == 0) {
            int v = ws[lane];
#pragma unroll
            for (int o = 16; o; o >>= 1) v += __shfl_xor_sync(0xffffffffu, v, o);
            if (lane == 0) s_pre = v;
        }
        __syncthreads();
    }

    int i = t * 4096 + tid * 4;
    int v[4];
    int s = 0;
#pragma unroll
    for (int q = 0; q < 4; q++) {
        int l = i + q;
        v[q] = (l < ng) ? deg[noff + l] : 0;
        s += v[q];
    }
    int incl = s;
#pragma unroll
    for (int o = 1; o < 32; o <<= 1) {
        int tv = __shfl_up_sync(0xffffffffu, incl, o);
        if (lane >= o) incl += tv;
    }
    __syncthreads();
    if (lane == 31) ws[w] = incl;
    __syncthreads();
    if (w == 0) {
        int x = ws[lane];
#pragma unroll
        for (int o = 1; o < 32; o <<= 1) {
            int tv = __shfl_up_sync(0xffffffffu, x, o);
            if (lane >= o) x += tv;
        }
        ws[lane] = x;
    }
    __syncthreads();
    int base = s_pre + (w > 0 ? ws[w - 1] : 0) + (incl - s);
    int run = base;
#pragma unroll
    for (int q = 0; q < 4; q++) {
        int l = i + q;
        if (l < ng) {
            rp[rpoff + l] = run;
            cur[noff + l] = run;
            dis[noff + l] = rsqrtf((float)(v[q] + 1));
            run += v[q];
        }
    }
    bool last = (t == ((ng + 4095) / 4096) - 1);
    if (last && tid == 1023) rp[rpoff + ng] = s_pre + ws[31];
}

// ---------------- CSR scatter: writes {src, dis[src]} pairs ----------------
__global__ void scatter8_k(const int* __restrict__ e0, const int* __restrict__ e1,
                           const int* __restrict__ e2, int* __restrict__ cur,
                           const float* __restrict__ dis, int2* __restrict__ es) {
    int i = blockIdx.x * blockDim.x + threadIdx.x;
    int i8 = i * 8;
    const int* pe;
    int nb, sb, E;
    if (i8 < E0)           { pe = e0; nb = 0;       sb = 0;       E = E0; }
    else if (i8 < E0 + E1) { pe = e1; nb = N0;      sb = E0;      E = E1; i8 -= E0; }
    else if (i8 < ET)      { pe = e2; nb = N0 + N1; sb = E0 + E1; E = E2; i8 -= E0 + E1; }
    else return;
    int4 c0 = *(const int4*)(pe + E + i8);
    int4 c1 = *(const int4*)(pe + E + i8 + 4);
    int4 r0 = *(const int4*)(pe + i8);
    int4 r1 = *(const int4*)(pe + i8 + 4);
    int p0 = atomicAdd(&cur[nb + c0.x], 1);
    int p1 = atomicAdd(&cur[nb + c0.y], 1);
    int p2 = atomicAdd(&cur[nb + c0.z], 1);
    int p3 = atomicAdd(&cur[nb + c0.w], 1);
    int p4 = atomicAdd(&cur[nb + c1.x], 1);
    int p5 = atomicAdd(&cur[nb + c1.y], 1);
    int p6 = atomicAdd(&cur[nb + c1.z], 1);
    int p7 = atomicAdd(&cur[nb + c1.w], 1);
    float d0 = dis[nb + r0.x], d1 = dis[nb + r0.y];
    float d2 = dis[nb + r0.z], d3 = dis[nb + r0.w];
    float d4 = dis[nb + r1.x], d5 = dis[nb + r1.y];
    float d6 = dis[nb + r1.z], d7 = dis[nb + r1.w];
    es[sb + p0] = make_int2(r0.x, __float_as_int(d0));
    es[sb + p1] = make_int2(r0.y, __float_as_int(d1));
    es[sb + p2] = make_int2(r0.z, __float_as_int(d2));
    es[sb + p3] = make_int2(r0.w, __float_as_int(d3));
    es[sb + p4] = make_int2(r1.x, __float_as_int(d4));
    es[sb + p5] = make_int2(r1.y, __float_as_int(d5));
    es[sb + p6] = make_int2(r1.z, __float_as_int(d6));
    es[sb + p7] = make_int2(r1.w, __float_as_int(d7));
}

// ---------------- tensor-core GEMM (tf32 mma.sync), persistent, double-buffered ----
#define WS_STRIDE 136
#define AS_STRIDE 132
#define SMEM_TC ((128 * WS_STRIDE + 2 * 128 * AS_STRIDE) * 4)

template<bool GATHER>
__global__ __launch_bounds__(512, 1) void gemm_tc(
    const float* __restrict__ A, const float* __restrict__ W,
    __half* __restrict__ C, int rows,
    const float* __restrict__ hsrc, int h_rows,
    const int* __restrict__ idx, const float* __restrict__ val,
    const float* __restrict__ enc)
{
    extern __shared__ float sm[];
    float* Ws = sm;
    float* As[2] = { sm + 128 * WS_STRIDE,
                     sm + 128 * WS_STRIDE + 128 * AS_STRIDE };
    int tid = threadIdx.x;
    int lane = tid & 31;
    int w = tid >> 5;
    int wm = w & 3, wn = w >> 2;
    int gid = lane >> 2, tig = lane & 3;

    int tiles = (rows + 127) >> 7;

#pragma unroll
    for (int j = 0; j < 8; j++) {
        int linear = tid + j * 512;
        int k = linear >> 5, c4 = linear & 31;
        float4 v = *(const float4*)(W + k * 128 + c4 * 4);
        uint4 q;
        q.x = tf32_of(v.x); q.y = tf32_of(v.y);
        q.z = tf32_of(v.z); q.w = tf32_of(v.w);
        *(uint4*)(Ws + k * WS_STRIDE + c4 * 4) = q;
    }

    float4 st[8];
    auto load_tile = [&](int tile) {
#pragma unroll
        for (int c = 0; c < 8; c++) {
            int r = w + c * 16;
            int gr = tile * 128 + r;
            float4 v = make_float4(0.f, 0.f, 0.f, 0.f);
            if (gr < rows) {
                if (GATHER) {
                    int ci = min(idx[gr], h_rows - 1);
                    float vv = val[gr];
                    float4 u = *(const float4*)(hsrc + (size_t)ci * D + lane * 4);
                    float4 e = *(const float4*)(enc + (size_t)gr * D + lane * 4);
                    v = make_float4(vv * u.x + e.x, vv * u.y + e.y,
                                    vv * u.z + e.z, vv * u.w + e.w);
                } else {
                    v = *(const float4*)(A + (size_t)gr * D + lane * 4);
                }
            }
            st[c] = v;
        }
    };
    auto store_tile = [&](float* dst) {
#pragma unroll
        for (int c = 0; c < 8; c++) {
            int r = w + c * 16;
            uint4 q;
            q.x = tf32_of(st[c].x); q.y = tf32_of(st[c].y);
            q.z = tf32_of(st[c].z); q.w = tf32_of(st[c].w);
            *(uint4*)(dst + r * AS_STRIDE + lane * 4) = q;
        }
    };

    int t = blockIdx.x;
    if (t < tiles) load_tile(t);
    store_tile(As[0]);
    __syncthreads();

    int buf = 0;
    for (; t < tiles; t += gridDim.x) {
        int tn = t + gridDim.x;
        bool hasnext = tn < tiles;
        if (hasnext) load_tile(tn);

        float acc[2][4][4];
#pragma unroll
        for (int mt = 0; mt < 2; mt++)
#pragma unroll
            for (int nt = 0; nt < 4; nt++)
#pragma unroll
                for (int q = 0; q < 4; q++) acc[mt][nt][q] = 0.f;

        const float* Ac = As[buf];
#pragma unroll 4
        for (int ks = 0; ks < 16; ks++) {
            int k0 = ks * 8;
            unsigned a[2][4];
#pragma unroll
            for (int mt = 0; mt < 2; mt++) {
                const float* base = Ac + (wm * 32 + mt * 16 + gid) * AS_STRIDE + k0 + tig;
                a[mt][0] = __float_as_uint(base[0]);
                a[mt][1] = __float_as_uint(base[8 * AS_STRIDE]);
                a[mt][2] = __float_as_uint(base[4]);
                a[mt][3] = __float_as_uint(base[8 * AS_STRIDE + 4]);
            }
#pragma unroll
            for (int nt = 0; nt < 4; nt++) {
                int n = wn * 32 + nt * 8 + gid;
                unsigned b0 = __float_as_uint(Ws[(k0 + tig) * WS_STRIDE + n]);
                unsigned b1 = __float_as_uint(Ws[(k0 + tig + 4) * WS_STRIDE + n]);
                mma_tf32(acc[0][nt], a[0], b0, b1);
                mma_tf32(acc[1][nt], a[1], b0, b1);
            }
        }

#pragma unroll
        for (int mt = 0; mt < 2; mt++) {
            int r1 = t * 128 + wm * 32 + mt * 16 + gid;
            int r2 = r1 + 8;
#pragma unroll
            for (int nt = 0; nt < 4; nt++) {
                int col = wn * 32 + nt * 8 + 2 * tig;
                if (r1 < rows)
                    *(__half2*)(C + (size_t)r1 * D + col) =
                        __floats2half2_rn(acc[mt][nt][0], acc[mt][nt][1]);
                if (r2 < rows)
                    *(__half2*)(C + (size_t)r2 * D + col) =
                        __floats2half2_rn(acc[mt][nt][2], acc[mt][nt][3]);
            }
        }

        if (hasnext) {
            store_tile(As[buf ^ 1]);
            __syncthreads();
            buf ^= 1;
        }
    }
}

// ---------------- aggregation (warp/dst, unroll4, fp16 gathers, {src,dis} pairs) ---
template<int MODE>   // 0 = plain, 1 = fused pool scatter, 2 = fused normalize
__global__ void agg_k(const __half* __restrict__ t, int h_rows,
                      const int* __restrict__ rp, const int2* __restrict__ es,
                      const float* __restrict__ dis, int n,
                      const float* __restrict__ bias, float* __restrict__ out,
                      const int* __restrict__ pidx, const float* __restrict__ pval,
                      float* __restrict__ pout) {
    int warp = (blockIdx.x * blockDim.x + threadIdx.x) >> 5;
    int lane = threadIdx.x & 31;
    if (warp >= n) return;
    int dst = warp;
    float dd = dis[dst];
    int hc = h_rows - 1;
    float4 v = ld_h4(t, (size_t)min(dst, hc), lane);
    float w0 = dd * dd;
    float4 a1 = make_float4(w0 * v.x, w0 * v.y, w0 * v.z, w0 * v.w);
    float4 a2 = make_float4(0.f, 0.f, 0.f, 0.f);
    float4 a3 = make_float4(0.f, 0.f, 0.f, 0.f);
    float4 a4 = make_float4(0.f, 0.f, 0.f, 0.f);
    int e = rp[dst], end = rp[dst + 1];
    for (; e + 4 <= end; e += 4) {
        int2 e0 = es[e], e1 = es[e + 1], e2 = es[e + 2], e3 = es[e + 3];
        float q0 = __int_as_float(e0.y) * dd, q1 = __int_as_float(e1.y) * dd;
        float q2 = __int_as_float(e2.y) * dd, q3 = __int_as_float(e3.y) * dd;
        float4 u0 = ld_h4(t, (size_t)min(e0.x, hc), lane);
        float4 u1 = ld_h4(t, (size_t)min(e1.x, hc), lane);
        float4 u2 = ld_h4(t, (size_t)min(e2.x, hc), lane);
        float4 u3 = ld_h4(t, (size_t)min(e3.x, hc), lane);
        a1.x += q0 * u0.x; a1.y += q0 * u0.y; a1.z += q0 * u0.z; a1.w += q0 * u0.w;
        a2.x += q1 * u1.x; a2.y += q1 * u1.y; a2.z += q1 * u1.z; a2.w += q1 * u1.w;
        a3.x += q2 * u2.x; a3.y += q2 * u2.y; a3.z += q2 * u2.z; a3.w += q2 * u2.w;
        a4.x += q3 * u3.x; a4.y += q3 * u3.y; a4.z += q3 * u3.z; a4.w += q3 * u3.w;
    }
    for (; e < end; e++) {
        int2 e0 = es[e];
        float q0 = __int_as_float(e0.y) * dd;
        float4 u0 = ld_h4(t, (size_t)min(e0.x, hc), lane);
        a1.x += q0 * u0.x; a1.y += q0 * u0.y; a1.z += q0 * u0.z; a1.w += q0 * u0.w;
    }
    float4 b = ((const float4*)bias)[lane];
    float4 r;
    r.x = fmaxf(a1.x + a2.x + a3.x + a4.x + b.x, 0.f);
    r.y = fmaxf(a1.y + a2.y + a3.y + a4.y + b.y, 0.f);
    r.z = fmaxf(a1.z + a2.z + a3.z + a4.z + b.z, 0.f);
    r.w = fmaxf(a1.w + a2.w + a3.w + a4.w + b.w, 0.f);
    if (MODE == 2) {
        float s = r.x * r.x + r.y * r.y + r.z * r.z + r.w * r.w;
#pragma unroll
        for (int o = 16; o; o >>= 1) s += __shfl_xor_sync(0xffffffffu, s, o);
        float inv = 1.0f / fmaxf(sqrtf(s), 1e-12f);
        r.x *= inv; r.y *= inv; r.z *= inv; r.w *= inv;
    }
    ((float4*)(out + (size_t)dst * D))[lane] = r;
    if (MODE == 1) {
        int c = pidx[dst];
        float pv = pval[dst];
        float* o = pout + (size_t)c * D + lane * 4;
        atomicAdd(o + 0, pv * r.x);
        atomicAdd(o + 1, pv * r.y);
        atomicAdd(o + 2, pv * r.z);
        atomicAdd(o + 3, pv * r.w);
    }
}

// ---------------- host orchestration ----------------
static inline int cdiv(int a, int b) { return (a + b - 1) / b; }

extern "C" void kernel_launch(void* const* d_in, const int* in_sizes, int n_in,
                              void* d_out, int out_size) {
    const float* x   = (const float*)d_in[0];
    const int* e0    = (const int*)d_in[1];
    const int* e1    = (const int*)d_in[2];
    const int* e2    = (const int*)d_in[3];
    const int* C0i   = (const int*)d_in[4];
    const float* C0v = (const float*)d_in[5];
    const int* C1i   = (const int*)d_in[6];
    const float* C1v = (const float*)d_in[7];
    const float* W_enc0 = (const float*)d_in[8];
    const float* b_enc0 = (const float*)d_in[9];
    const float* W_enc1 = (const float*)d_in[10];
    const float* b_enc1 = (const float*)d_in[11];
    const float* W_enc2 = (const float*)d_in[12];
    const float* b_enc2 = (const float*)d_in[13];
    const float* W_bot  = (const float*)d_in[14];
    const float* b_bot  = (const float*)d_in[15];
    const float* W_dec0 = (const float*)d_in[16];
    const float* b_dec0 = (const float*)d_in[17];
    const float* W_dec1 = (const float*)d_in[18];
    const float* b_dec1 = (const float*)d_in[19];
    const float* W_dec2 = (const float*)d_in[20];
    const float* b_dec2 = (const float*)d_in[21];

    __half* t;
    float *enc0, *enc1, *h, *h2, *dis;
    int *deg, *rp, *cur;
    int2* es;
    cudaGetSymbolAddress((void**)&t, g_t);
    cudaGetSymbolAddress((void**)&enc0, g_enc0);
    cudaGetSymbolAddress((void**)&enc1, g_enc1);
    cudaGetSymbolAddress((void**)&h, g_h);
    cudaGetSymbolAddress((void**)&h2, g_h2);
    cudaGetSymbolAddress((void**)&deg, g_deg);
    cudaGetSymbolAddress((void**)&rp, g_rp);
    cudaGetSymbolAddress((void**)&cur, g_cur);
    cudaGetSymbolAddress((void**)&es, g_es);
    cudaGetSymbolAddress((void**)&dis, g_dis);

    cudaFuncSetAttribute((const void*)gemm_tc<false>, cudaFuncAttributeMaxDynamicSharedMemorySize, SMEM_TC);
    cudaFuncSetAttribute((const void*)gemm_tc<true>,  cudaFuncAttributeMaxDynamicSharedMemorySize, SMEM_TC);

    const int* rp0 = rp + RP0; const int2* es0 = es;           const float* dis0 = dis;
    const int* rp1 = rp + RP1; const int2* es1 = es + E0;      const float* dis1 = dis + N0;
    const int* rp2 = rp + RP2; const int2* es2 = es + E0 + E1; const float* dis2 = dis + N0 + N1;

    const int AT = 256;

    auto gemm = [&](const float* A, const float* W, int rows) {
        int grid = min(cdiv(rows, 128), 148);
        gemm_tc<false><<<grid, 512, SMEM_TC>>>(A, W, t, rows, nullptr, 0, nullptr, nullptr, nullptr);
    };
    auto gemm_g = [&](const float* W, int rows, const float* hsrc, int h_rows,
                      const int* idx, const float* val, const float* enc) {
        int grid = min(cdiv(rows, 128), 148);
        gemm_tc<true><<<grid, 512, SMEM_TC>>>(nullptr, W, t, rows, hsrc, h_rows, idx, val, enc);
    };

    // ---- CSR build + zero h(N1) / h2(N2) ----
    zero_init_k<<<cdiv(NT, 1024), 1024>>>(deg, (float4*)h, (float4*)h2);
    hist8_k<<<cdiv(ET / 8, 256), 256>>>(e0, e1, e2, deg);
    scan_fused_k<<<NB, 1024>>>(deg, rp, cur, dis);
    scatter8_k<<<cdiv(ET / 8, 256), 256>>>(e0, e1, e2, cur, dis, es);

    // ---- encoder level 0: agg fuses pool0 -> h (N1 rows) ----
    gemm(x, W_enc0, N0);
    agg_k<1><<<cdiv(N0, 8), AT>>>(t, N0, rp0, es0, dis0, N0, b_enc0, enc0, C0i, C0v, h);
    // ---- encoder level 1: agg fuses pool1 -> h2 (N2 rows, pre-zeroed) ----
    gemm(h, W_enc1, N1);
    agg_k<1><<<cdiv(N1, 8), AT>>>(t, N1, rp1, es1, dis1, N1, b_enc1, enc1, C1i, C1v, h2);
    // ---- encoder level 2: h2 -> h ----
    gemm(h2, W_enc2, N2);
    agg_k<0><<<cdiv(N2, 8), AT>>>(t, N2, rp2, es2, dis2, N2, b_enc2, h, nullptr, nullptr, nullptr);
    // ---- bottleneck: h -> h2 ----
    gemm(h, W_bot, N2);
    agg_k<0><<<cdiv(N2, 8), AT>>>(t, N2, rp2, es2, dis2, N2, b_bot, h2, nullptr, nullptr, nullptr);
    // ---- decoder l=2: unpool C1 from h2 (N2 rows), conv g2 -> h ----
    gemm_g(W_dec2, N1, h2, N2, C1i, C1v, enc1);
    agg_k<0><<<cdiv(N2, 8), AT>>>(t, N1, rp2, es2, dis2, N2, b_dec2, h, nullptr, nullptr, nullptr);
    // ---- decoder l=1: unpool C0 from h (N2 rows, clamped), conv g1 -> h2 ----
    gemm_g(W_dec1, N0, h, N2, C0i, C0v, enc0);
    agg_k<0><<<cdiv(N1, 8), AT>>>(t, N0, rp1, es1, dis1, N1, b_dec1, h2, nullptr, nullptr, nullptr);
    // ---- decoder l=0 + fused normalize: h2 (N1 rows) -> out ----
    gemm(h2, W_dec0, N1);
    agg_k<2><<<cdiv(N0, 8), AT>>>(t, N1, rp0, es0, dis0, N0, b_dec0, (float*)d_out, nullptr, nullptr, nullptr);
}